// round 5
// baseline (speedup 1.0000x reference)
#include <cuda_runtime.h>
#include <cuda_bf16.h>
#include <math.h>
#include <stdint.h>

#define BB 8
#define HWN 4096

// -------- scratch (allocation-free rule: __device__ globals) --------
__device__ uint8_t g_Q8[BB*HWN*64];   // e4m3 [b][p][ci]
__device__ uint8_t g_K8[BB*HWN*64];   // e4m3 [b][p][ci]
__device__ uint8_t g_V8[BB*64*HWN];   // e4m3 [b][ci][p] (transposed)
__device__ float g_AO[BB*HWN*64];     // attention output [b][p][d]
__device__ float g_SW[BB*128*HWN];    // sigmoid gates [b][ci][p]

__device__ __forceinline__ uint16_t pack_e4m3x2(float lo, float hi) {
  uint16_t r;
  asm("cvt.rn.satfinite.e4m3x2.f32 %0, %1, %2;" : "=h"(r) : "f"(hi), "f"(lo));
  return r;
}
__device__ __forceinline__ uint32_t pack_e4m3x4(float f0, float f1, float f2, float f3) {
  uint16_t lo = pack_e4m3x2(f0, f1), hi = pack_e4m3x2(f2, f3);
  return (uint32_t)lo | ((uint32_t)hi << 16);
}

// ===================================================================
// Kernel 1: fused gf-build (upsample+concat) + QKV 1x1 convs
// ===================================================================
__global__ void qkv_kernel(const float* __restrict__ x1, const float* __restrict__ x2,
                           const float* __restrict__ x3, const float* __restrict__ x4,
                           const float* __restrict__ qw, const float* __restrict__ qb,
                           const float* __restrict__ kw, const float* __restrict__ kb,
                           const float* __restrict__ vw, const float* __restrict__ vb) {
  extern __shared__ float sh[];
  float* wst  = sh;                    // [128][192]
  float* gfs  = wst + 128*192;         // [128][68]
  float* bias = gfs + 128*68;          // [192]
  float* outs = bias + 192;            // [192][65]
  const int b = blockIdx.y, y = blockIdx.x, tid = threadIdx.x;

  for (int i = tid; i < 64*128; i += 256) {
    int ci = i >> 7, c = i & 127;
    wst[c*192 + ci]       = qw[i];
    wst[c*192 + 64 + ci]  = kw[i];
    wst[c*192 + 128 + ci] = vw[i];
  }
  for (int i = tid; i < 192; i += 256)
    bias[i] = (i < 64) ? qb[i] : (i < 128 ? kb[i-64] : vb[i-128]);

  for (int i = tid; i < 32*64; i += 256) {
    int c = i >> 6, x = i & 63;
    gfs[c*68 + x] = x1[((b*32 + c)*64 + y)*64 + x];
  }
  const float* srcs[3] = {x2, x3, x4};
  const int    Hs[3]   = {32, 16, 8};
  #pragma unroll
  for (int lvl = 0; lvl < 3; lvl++) {
    const int H = Hs[lvl];
    const float* src = srcs[lvl];
    float fy = (float)y * (float)(H-1) / 63.0f;
    int y0 = (int)fy; if (y0 > H-1) y0 = H-1;
    int y1i = min(y0+1, H-1);
    float wy = fy - (float)y0;
    for (int i = tid; i < 32*64; i += 256) {
      int c = i >> 6, x = i & 63;
      float fx = (float)x * (float)(H-1) / 63.0f;
      int x0 = (int)fx; if (x0 > H-1) x0 = H-1;
      int x1i = min(x0+1, H-1);
      float wx = fx - (float)x0;
      const float* r0 = src + ((b*32 + c)*H + y0)*H;
      const float* r1 = src + ((b*32 + c)*H + y1i)*H;
      float top = r0[x0]*(1.f-wx) + r0[x1i]*wx;
      float bot = r1[x0]*(1.f-wx) + r1[x1i]*wx;
      gfs[(32*(lvl+1) + c)*68 + x] = top*(1.f-wy) + bot*wy;
    }
  }
  __syncthreads();

  const int tx = tid & 15, ty = tid >> 4;
  float acc[12][4];
  #pragma unroll
  for (int i = 0; i < 12; i++) { acc[i][0]=acc[i][1]=acc[i][2]=acc[i][3]=0.f; }
  for (int c = 0; c < 128; c++) {
    float4 g = *(const float4*)&gfs[c*68 + tx*4];
    const float* wr = &wst[c*192 + ty*12];
    float4 w0 = *(const float4*)&wr[0];
    float4 w1 = *(const float4*)&wr[4];
    float4 w2 = *(const float4*)&wr[8];
    float wv[12] = {w0.x,w0.y,w0.z,w0.w, w1.x,w1.y,w1.z,w1.w, w2.x,w2.y,w2.z,w2.w};
    #pragma unroll
    for (int i = 0; i < 12; i++) {
      acc[i][0] += wv[i]*g.x; acc[i][1] += wv[i]*g.y;
      acc[i][2] += wv[i]*g.z; acc[i][3] += wv[i]*g.w;
    }
  }
  #pragma unroll
  for (int i = 0; i < 12; i++) {
    int row = ty*12 + i;
    float bbv = bias[row];
    #pragma unroll
    for (int j = 0; j < 4; j++)
      outs[row*65 + tx*4 + j] = acc[i][j] + bbv;
  }
  __syncthreads();

  // writeout: Q,K e4m3 [p][64]; V e4m3 transposed [d][p]
  const int pbase = b*HWN + y*64;
  uint32_t* Q8 = (uint32_t*)g_Q8 + (size_t)pbase*16;
  uint32_t* K8 = (uint32_t*)g_K8 + (size_t)pbase*16;
  for (int i = tid; i < 1024; i += 256) {
    int p = i >> 4, c = i & 15;
    Q8[p*16 + c] = pack_e4m3x4(outs[(4*c)*65 + p],   outs[(4*c+1)*65 + p],
                               outs[(4*c+2)*65 + p], outs[(4*c+3)*65 + p]);
    K8[p*16 + c] = pack_e4m3x4(outs[(64+4*c)*65 + p],   outs[(64+4*c+1)*65 + p],
                               outs[(64+4*c+2)*65 + p], outs[(64+4*c+3)*65 + p]);
  }
  uint32_t* V8 = (uint32_t*)g_V8;
  for (int i = tid; i < 1024; i += 256) {
    int d = i >> 4, c = i & 15;
    const float* vr = &outs[(128+d)*65];
    V8[((size_t)(b*64+d)*HWN + y*64)/4 + c] =
        pack_e4m3x4(vr[4*c], vr[4*c+1], vr[4*c+2], vr[4*c+3]);
  }
}

// ===================================================================
// Kernel 2: fp8(e4m3) tensor-core flash attention, d=64, seq=4096
// grid (32 q-tiles of 128, B), 256 threads (8 warps x 16 rows), 2 CTA/SM
// ===================================================================
#define KVSTRIDE 80                  // padded row stride (bytes), conflict-free
#define KTILE (64*KVSTRIDE)          // 5120 B
#define STAGE (2*KTILE)              // K + V = 10240 B
#define SM_P  (2*STAGE)              // P strips start at 20480
#define SM_ATTN (SM_P + 8*1280)      // 30720 B total

__device__ __forceinline__ void cp_async16(uint32_t smem_dst, const void* gsrc) {
  asm volatile("cp.async.ca.shared.global [%0], [%1], 16;\n" :: "r"(smem_dst), "l"(gsrc));
}

__device__ __forceinline__ void mma_fp8(float d[4], const uint32_t a[4],
                                        uint32_t b0, uint32_t b1) {
  asm volatile("mma.sync.aligned.m16n8k32.row.col.f32.e4m3.e4m3.f32 "
               "{%0,%1,%2,%3}, {%4,%5,%6,%7}, {%8,%9}, {%0,%1,%2,%3};"
               : "+f"(d[0]), "+f"(d[1]), "+f"(d[2]), "+f"(d[3])
               : "r"(a[0]), "r"(a[1]), "r"(a[2]), "r"(a[3]), "r"(b0), "r"(b1));
}

__device__ __forceinline__ void prefetch_kv(uint32_t sbase, int b, int jt, int stage, int tid) {
  uint32_t st = sbase + (uint32_t)stage * STAGE;
  const uint8_t* Ks = g_K8 + ((size_t)b*HWN + jt*64)*64;
  const uint8_t* Vs = g_V8 + (size_t)b*64*HWN + jt*64;
  #pragma unroll
  for (int it = 0; it < 2; it++) {
    int i = tid + it*256;            // 0..511
    if (i < 256) {                   // K: 64 rows x 4 chunks of 16B
      int r = i >> 2, c = i & 3;
      cp_async16(st + (uint32_t)(r*KVSTRIDE + c*16), Ks + r*64 + c*16);
    } else {                         // V: 64 d-rows x 4 chunks of 16B
      int j = i - 256, r = j >> 2, c = j & 3;
      cp_async16(st + KTILE + (uint32_t)(r*KVSTRIDE + c*16), Vs + (size_t)r*HWN + c*16);
    }
  }
}

__global__ void __launch_bounds__(256, 2) attn_kernel() {
  extern __shared__ char smem[];
  uint32_t sbase;
  asm("{ .reg .u64 t; cvta.to.shared.u64 t, %1; cvt.u32.u64 %0, t; }"
      : "=r"(sbase) : "l"(smem));
  const int b = blockIdx.y, m0 = blockIdx.x*128;
  const int tid = threadIdx.x, w = tid >> 5, lane = tid & 31;
  const int g = lane >> 2, t = lane & 3;

  // Q fragments (fp8, m16n8k32 A layout), resident in registers
  const uint8_t* Qg = g_Q8 + ((size_t)b*HWN + m0 + w*16)*64;
  uint32_t qa[2][4];
  #pragma unroll
  for (int kt = 0; kt < 2; kt++) {
    qa[kt][0] = *(const uint32_t*)(Qg +  g   *64 + kt*32 + 4*t);
    qa[kt][1] = *(const uint32_t*)(Qg + (g+8)*64 + kt*32 + 4*t);
    qa[kt][2] = *(const uint32_t*)(Qg +  g   *64 + kt*32 + 4*t + 16);
    qa[kt][3] = *(const uint32_t*)(Qg + (g+8)*64 + kt*32 + 4*t + 16);
  }

  const uint32_t psm = sbase + SM_P + (uint32_t)w*1280;
  float m0r = -1e30f, m1r = -1e30f, l0 = 0.f, l1 = 0.f;
  float o[8][4] = {};

  prefetch_kv(sbase, b, 0, 0, tid);
  asm volatile("cp.async.commit_group;\n" ::: "memory");

  for (int jt = 0; jt < 64; jt++) {
    if (jt + 1 < 64) {
      prefetch_kv(sbase, b, jt+1, (jt+1)&1, tid);
      asm volatile("cp.async.commit_group;\n" ::: "memory");
      asm volatile("cp.async.wait_group 1;\n" ::: "memory");
    } else {
      asm volatile("cp.async.wait_group 0;\n" ::: "memory");
    }
    __syncthreads();

    const uint32_t* K32 = (const uint32_t*)(smem + (jt&1)*STAGE);
    const uint32_t* V32 = K32 + KTILE/4;

    // ---- S = Q K^T (16 rows x 64 keys per warp) ----
    float s[8][4] = {};
    #pragma unroll
    for (int kt = 0; kt < 2; kt++) {
      #pragma unroll
      for (int nt = 0; nt < 8; nt++) {
        uint32_t b0 = K32[(nt*8 + g)*(KVSTRIDE/4) + kt*8 + t];
        uint32_t b1 = K32[(nt*8 + g)*(KVSTRIDE/4) + kt*8 + t + 4];
        mma_fp8(s[nt], qa[kt], b0, b1);
      }
    }

    // ---- online softmax (rows g and g+8) ----
    float rmax0 = -1e30f, rmax1 = -1e30f;
    #pragma unroll
    for (int nt = 0; nt < 8; nt++) {
      rmax0 = fmaxf(rmax0, fmaxf(s[nt][0], s[nt][1]));
      rmax1 = fmaxf(rmax1, fmaxf(s[nt][2], s[nt][3]));
    }
    rmax0 = fmaxf(rmax0, __shfl_xor_sync(0xffffffffu, rmax0, 1));
    rmax0 = fmaxf(rmax0, __shfl_xor_sync(0xffffffffu, rmax0, 2));
    rmax1 = fmaxf(rmax1, __shfl_xor_sync(0xffffffffu, rmax1, 1));
    rmax1 = fmaxf(rmax1, __shfl_xor_sync(0xffffffffu, rmax1, 2));
    float mn0 = fmaxf(m0r, rmax0), mn1 = fmaxf(m1r, rmax1);
    float c0 = __expf(m0r - mn0), c1 = __expf(m1r - mn1);
    m0r = mn0; m1r = mn1;
    float rs0 = 0.f, rs1 = 0.f;
    #pragma unroll
    for (int nt = 0; nt < 8; nt++) {
      s[nt][0] = __expf(s[nt][0] - mn0);
      s[nt][1] = __expf(s[nt][1] - mn0);
      s[nt][2] = __expf(s[nt][2] - mn1);
      s[nt][3] = __expf(s[nt][3] - mn1);
      rs0 += s[nt][0] + s[nt][1];
      rs1 += s[nt][2] + s[nt][3];
    }
    rs0 += __shfl_xor_sync(0xffffffffu, rs0, 1);
    rs0 += __shfl_xor_sync(0xffffffffu, rs0, 2);
    rs1 += __shfl_xor_sync(0xffffffffu, rs1, 1);
    rs1 += __shfl_xor_sync(0xffffffffu, rs1, 2);
    l0 = l0*c0 + rs0;  l1 = l1*c1 + rs1;
    #pragma unroll
    for (int nt = 0; nt < 8; nt++) {
      o[nt][0] *= c0; o[nt][1] *= c0; o[nt][2] *= c1; o[nt][3] *= c1;
    }

    // ---- P -> e4m3 via per-warp smem strip, reload as fp8 A-frags ----
    #pragma unroll
    for (int nt = 0; nt < 8; nt++) {
      uint16_t pg  = pack_e4m3x2(s[nt][0], s[nt][1]);
      uint16_t pg8 = pack_e4m3x2(s[nt][2], s[nt][3]);
      asm volatile("st.shared.u16 [%0], %1;"
                   :: "r"(psm + (uint32_t)( g   *KVSTRIDE + nt*8 + 2*t)), "h"(pg)  : "memory");
      asm volatile("st.shared.u16 [%0], %1;"
                   :: "r"(psm + (uint32_t)((g+8)*KVSTRIDE + nt*8 + 2*t)), "h"(pg8) : "memory");
    }
    __syncwarp();
    uint32_t pa[2][4];
    {
      uint32_t prow = lane & 15, pbyte = (lane >> 4) * 16;
      #pragma unroll
      for (int kt = 0; kt < 2; kt++) {
        uint32_t addr = psm + prow*KVSTRIDE + pbyte + kt*32;
        asm volatile("ldmatrix.sync.aligned.m8n8.x4.shared.b16 {%0,%1,%2,%3}, [%4];"
                     : "=r"(pa[kt][0]), "=r"(pa[kt][1]), "=r"(pa[kt][2]), "=r"(pa[kt][3])
                     : "r"(addr));
      }
    }

    // ---- O += P V ----
    #pragma unroll
    for (int kt = 0; kt < 2; kt++) {
      #pragma unroll
      for (int nt = 0; nt < 8; nt++) {
        uint32_t b0 = V32[(nt*8 + g)*(KVSTRIDE/4) + kt*8 + t];
        uint32_t b1 = V32[(nt*8 + g)*(KVSTRIDE/4) + kt*8 + t + 4];
        mma_fp8(o[nt], pa[kt], b0, b1);
      }
    }
    __syncthreads();   // all reads of this stage done before refill
  }

  float* AO = g_AO + ((size_t)b*HWN + m0 + w*16)*64;
  float i0 = 1.f / l0, i1 = 1.f / l1;
  #pragma unroll
  for (int nt = 0; nt < 8; nt++) {
    *(float2*)&AO[ g   *64 + nt*8 + 2*t] = make_float2(o[nt][0]*i0, o[nt][1]*i0);
    *(float2*)&AO[(g+8)*64 + nt*8 + 2*t] = make_float2(o[nt][2]*i1, o[nt][3]*i1);
  }
}

// ===================================================================
// Kernel 3: out-proj + gate MLP + sigmoid  (attn_out -> g_SW)
// ===================================================================
__global__ void proj_kernel(const float* __restrict__ ow_, const float* __restrict__ ob,
                            const float* __restrict__ g1w, const float* __restrict__ g1b,
                            const float* __restrict__ g2w, const float* __restrict__ g2b) {
  extern __shared__ float sh[];
  float* owt  = sh;              // [64][128]
  float* g1wt = owt + 8192;      // [128][32]
  float* g2wt = g1wt + 4096;     // [32][128]
  float* obs  = g2wt + 4096;     // 128
  float* g1bs = obs + 128;       // 32
  float* g2bs = g1bs + 32;       // 128
  float* ao   = g2bs + 128;      // [32][64]
  float* gf2  = ao + 2048;       // [32][128]
  float* hb   = gf2 + 4096;      // [32][32]
  float* swt  = hb + 1024;       // [128][32]
  const int b = blockIdx.y, p0 = blockIdx.x*32, tid = threadIdx.x;

  for (int i = tid; i < 8192; i += 256) { int ci = i>>6, d = i&63;  owt [d*128+ci] = ow_[i]; }
  for (int i = tid; i < 4096; i += 256) { int co = i>>7, c = i&127; g1wt[c*32 +co] = g1w[i]; }
  for (int i = tid; i < 4096; i += 256) { int ci = i>>5, c = i&31;  g2wt[c*128+ci] = g2w[i]; }
  for (int i = tid; i < 128;  i += 256) obs[i]  = ob[i];
  for (int i = tid; i < 32;   i += 256) g1bs[i] = g1b[i];
  for (int i = tid; i < 128;  i += 256) g2bs[i] = g2b[i];
  const float* AOg = g_AO + ((size_t)b*HWN + p0)*64;
  for (int i = tid; i < 2048; i += 256) ao[i] = AOg[i];
  __syncthreads();

  for (int o = tid; o < 4096; o += 256) {
    int p = o >> 7, ci = o & 127;
    float s = obs[ci];
    const float* av = &ao[p*64];
    #pragma unroll 8
    for (int d = 0; d < 64; d++) s += owt[d*128+ci]*av[d];
    gf2[o] = s;
  }
  __syncthreads();
  for (int o = tid; o < 1024; o += 256) {
    int p = o >> 5, co = o & 31;
    float s = g1bs[co];
    const float* gv = &gf2[p*128];
    #pragma unroll 8
    for (int c = 0; c < 128; c++) s += g1wt[c*32+co]*gv[c];
    hb[o] = fmaxf(s, 0.f);
  }
  __syncthreads();
  for (int o = tid; o < 4096; o += 256) {
    int p = o >> 7, ci = o & 127;
    float s = g2bs[ci];
    const float* hv = &hb[p*32];
    #pragma unroll
    for (int c = 0; c < 32; c++) s += g2wt[c*128+ci]*hv[c];
    swt[ci*32 + p] = 1.f/(1.f + __expf(-s));
  }
  __syncthreads();
  for (int o = tid; o < 4096; o += 256) {
    int ci = o >> 5, pp = o & 31;
    g_SW[((size_t)b*128+ci)*HWN + p0 + pp] = swt[o];
  }
}

// ===================================================================
// Kernel 4: final gating (with bilinear resample of gates for x2..x4)
// ===================================================================
__device__ __forceinline__ float sample_sw(const float* __restrict__ plane, int y, int x, int OH) {
  float fy = (float)y * 63.0f / (float)(OH-1);
  float fx = (float)x * 63.0f / (float)(OH-1);
  int y0 = (int)fy; if (y0 > 63) y0 = 63;
  int x0 = (int)fx; if (x0 > 63) x0 = 63;
  int y1 = min(y0+1, 63), x1 = min(x0+1, 63);
  float wy = fy - (float)y0, wx = fx - (float)x0;
  float a = plane[y0*64+x0], bv = plane[y0*64+x1];
  float c = plane[y1*64+x0], d = plane[y1*64+x1];
  return (a*(1.f-wx)+bv*wx)*(1.f-wy) + (c*(1.f-wx)+d*wx)*wy;
}

__global__ void gate_kernel(const float* __restrict__ x1, const float* __restrict__ x2,
                            const float* __restrict__ x3, const float* __restrict__ x4,
                            float* __restrict__ out) {
  int idx = blockIdx.x*256 + threadIdx.x;
  const int N1 = BB*32*4096, N2 = BB*32*1024, N3 = BB*32*256, N4 = BB*32*64;
  if (idx < N1) {
    int b = idx >> 17, c = (idx >> 12) & 31, p = idx & 4095;
    out[idx] = x1[idx]*(1.f + g_SW[((size_t)b*128 + c)*HWN + p]);
  } else if (idx < N1+N2) {
    int i = idx - N1;
    int b = i >> 15, c = (i >> 10) & 31, y = (i >> 5) & 31, x = i & 31;
    const float* plane = g_SW + ((size_t)b*128 + 32 + c)*HWN;
    out[idx] = x2[i]*(1.f + sample_sw(plane, y, x, 32));
  } else if (idx < N1+N2+N3) {
    int i = idx - N1 - N2;
    int b = i >> 13, c = (i >> 8) & 31, y = (i >> 4) & 15, x = i & 15;
    const float* plane = g_SW + ((size_t)b*128 + 64 + c)*HWN;
    out[idx] = x3[i]*(1.f + sample_sw(plane, y, x, 16));
  } else if (idx < N1+N2+N3+N4) {
    int i = idx - N1 - N2 - N3;
    int b = i >> 11, c = (i >> 6) & 31, y = (i >> 3) & 7, x = i & 7;
    const float* plane = g_SW + ((size_t)b*128 + 96 + c)*HWN;
    out[idx] = x4[i]*(1.f + sample_sw(plane, y, x, 8));
  }
}

// ===================================================================
extern "C" void kernel_launch(void* const* d_in, const int* in_sizes, int n_in,
                              void* d_out, int out_size) {
  const float* x1  = (const float*)d_in[0];
  const float* x2  = (const float*)d_in[1];
  const float* x3  = (const float*)d_in[2];
  const float* x4  = (const float*)d_in[3];
  const float* qw  = (const float*)d_in[4];
  const float* qb  = (const float*)d_in[5];
  const float* kw  = (const float*)d_in[6];
  const float* kb  = (const float*)d_in[7];
  const float* vw  = (const float*)d_in[8];
  const float* vb  = (const float*)d_in[9];
  const float* ow_ = (const float*)d_in[10];
  const float* ob  = (const float*)d_in[11];
  const float* g1w = (const float*)d_in[12];
  const float* g1b = (const float*)d_in[13];
  const float* g2w = (const float*)d_in[14];
  const float* g2b = (const float*)d_in[15];
  float* out = (float*)d_out;

  const int QKV_SMEM  = (128*192 + 128*68 + 192 + 192*65) * 4;  // 183808 B
  const int PROJ_SMEM = (8192+4096+4096+128+32+128+2048+4096+1024+4096) * 4; // 111360 B

  cudaFuncSetAttribute(qkv_kernel,  cudaFuncAttributeMaxDynamicSharedMemorySize, QKV_SMEM);
  cudaFuncSetAttribute(attn_kernel, cudaFuncAttributeMaxDynamicSharedMemorySize, SM_ATTN);
  cudaFuncSetAttribute(proj_kernel, cudaFuncAttributeMaxDynamicSharedMemorySize, PROJ_SMEM);

  qkv_kernel <<<dim3(64, BB),  256, QKV_SMEM >>>(x1, x2, x3, x4, qw, qb, kw, kb, vw, vb);
  attn_kernel<<<dim3(32, BB),  256, SM_ATTN  >>>();
  proj_kernel<<<dim3(128, BB), 256, PROJ_SMEM>>>(ow_, ob, g1w, g1b, g2w, g2b);

  const int TOTAL = BB*32*(4096 + 1024 + 256 + 64);  // 1392640
  gate_kernel<<<(TOTAL + 255)/256, 256>>>(x1, x2, x3, x4, out);
}

// round 6
// speedup vs baseline: 1.0876x; 1.0876x over previous
#include <cuda_runtime.h>
#include <cuda_fp16.h>
#include <math.h>
#include <stdint.h>

#define BB 8
#define HWN 4096

// -------- scratch (allocation-free rule: __device__ globals) --------
__device__ __half g_Qh[BB*HWN*64];   // [b][p][ci]
__device__ __half g_Kh[BB*HWN*64];   // [b][p][ci]
__device__ __half g_Vh[BB*64*HWN];   // [b][ci][p]  (transposed)
__device__ float g_AO[BB*HWN*64];    // attention output [b][p][d]
__device__ float g_SW[BB*128*HWN];   // sigmoid gates [b][ci][p]

__device__ __forceinline__ uint32_t pack_f16x2(float lo, float hi) {
  uint32_t r;
  asm("cvt.rn.f16x2.f32 %0, %1, %2;" : "=r"(r) : "f"(hi), "f"(lo));
  return r;
}

// ===================================================================
// Kernel 1: fused gf-build (upsample+concat) + QKV 1x1 convs
// ===================================================================
__global__ void qkv_kernel(const float* __restrict__ x1, const float* __restrict__ x2,
                           const float* __restrict__ x3, const float* __restrict__ x4,
                           const float* __restrict__ qw, const float* __restrict__ qb,
                           const float* __restrict__ kw, const float* __restrict__ kb,
                           const float* __restrict__ vw, const float* __restrict__ vb) {
  extern __shared__ float sh[];
  float* wst  = sh;                    // [128][192]
  float* gfs  = wst + 128*192;         // [128][68]
  float* bias = gfs + 128*68;          // [192]
  float* outs = bias + 192;            // [192][65]
  const int b = blockIdx.y, y = blockIdx.x, tid = threadIdx.x;

  for (int i = tid; i < 64*128; i += 256) {
    int ci = i >> 7, c = i & 127;
    wst[c*192 + ci]       = qw[i];
    wst[c*192 + 64 + ci]  = kw[i];
    wst[c*192 + 128 + ci] = vw[i];
  }
  for (int i = tid; i < 192; i += 256)
    bias[i] = (i < 64) ? qb[i] : (i < 128 ? kb[i-64] : vb[i-128]);

  for (int i = tid; i < 32*64; i += 256) {
    int c = i >> 6, x = i & 63;
    gfs[c*68 + x] = x1[((b*32 + c)*64 + y)*64 + x];
  }
  const float* srcs[3] = {x2, x3, x4};
  const int    Hs[3]   = {32, 16, 8};
  #pragma unroll
  for (int lvl = 0; lvl < 3; lvl++) {
    const int H = Hs[lvl];
    const float* src = srcs[lvl];
    float fy = (float)y * (float)(H-1) / 63.0f;
    int y0 = (int)fy; if (y0 > H-1) y0 = H-1;
    int y1i = min(y0+1, H-1);
    float wy = fy - (float)y0;
    for (int i = tid; i < 32*64; i += 256) {
      int c = i >> 6, x = i & 63;
      float fx = (float)x * (float)(H-1) / 63.0f;
      int x0 = (int)fx; if (x0 > H-1) x0 = H-1;
      int x1i = min(x0+1, H-1);
      float wx = fx - (float)x0;
      const float* r0 = src + ((b*32 + c)*H + y0)*H;
      const float* r1 = src + ((b*32 + c)*H + y1i)*H;
      float top = r0[x0]*(1.f-wx) + r0[x1i]*wx;
      float bot = r1[x0]*(1.f-wx) + r1[x1i]*wx;
      gfs[(32*(lvl+1) + c)*68 + x] = top*(1.f-wy) + bot*wy;
    }
  }
  __syncthreads();

  const int tx = tid & 15, ty = tid >> 4;
  float acc[12][4];
  #pragma unroll
  for (int i = 0; i < 12; i++) { acc[i][0]=acc[i][1]=acc[i][2]=acc[i][3]=0.f; }
  for (int c = 0; c < 128; c++) {
    float4 g = *(const float4*)&gfs[c*68 + tx*4];
    const float* wr = &wst[c*192 + ty*12];
    float4 w0 = *(const float4*)&wr[0];
    float4 w1 = *(const float4*)&wr[4];
    float4 w2 = *(const float4*)&wr[8];
    float wv[12] = {w0.x,w0.y,w0.z,w0.w, w1.x,w1.y,w1.z,w1.w, w2.x,w2.y,w2.z,w2.w};
    #pragma unroll
    for (int i = 0; i < 12; i++) {
      acc[i][0] += wv[i]*g.x; acc[i][1] += wv[i]*g.y;
      acc[i][2] += wv[i]*g.z; acc[i][3] += wv[i]*g.w;
    }
  }
  #pragma unroll
  for (int i = 0; i < 12; i++) {
    int row = ty*12 + i;
    float bbv = bias[row];
    #pragma unroll
    for (int j = 0; j < 4; j++)
      outs[row*65 + tx*4 + j] = acc[i][j] + bbv;
  }
  __syncthreads();

  // writeout: Q,K f16 [p][64]; V f16 transposed [d][p]
  const int pbase = b*HWN + y*64;
  uint32_t* Qu = (uint32_t*)g_Qh + (size_t)pbase*32;
  uint32_t* Ku = (uint32_t*)g_Kh + (size_t)pbase*32;
  for (int i = tid; i < 2048; i += 256) {
    int p = i >> 5, c2 = i & 31;
    Qu[p*32 + c2] = pack_f16x2(outs[(2*c2)*65 + p],     outs[(2*c2+1)*65 + p]);
    Ku[p*32 + c2] = pack_f16x2(outs[(64+2*c2)*65 + p],  outs[(65+2*c2)*65 + p]);
  }
  uint32_t* Vu = (uint32_t*)g_Vh;
  for (int i = tid; i < 2048; i += 256) {
    int d = i >> 5, px = i & 31;
    const float* vr = &outs[(128+d)*65];
    Vu[((size_t)(b*64+d)*HWN + y*64)/2 + px] = pack_f16x2(vr[2*px], vr[2*px+1]);
  }
}

// ===================================================================
// Kernel 2: f16 tensor-core flash attention (f16-acc QK, f32-acc PV)
// grid (32 q-tiles of 128, B), 256 threads (8 warps x 16 rows), 2 CTA/SM
// ===================================================================
#define KVW 36                       // row stride in u32 (72 halves)
#define KBYTES (64*KVW*4)            // 9216 B per tile
#define STAGE_BYTES (2*KBYTES)       // K + V = 18432 B

__device__ __forceinline__ void cp_async16(uint32_t smem_dst, const void* gsrc) {
  asm volatile("cp.async.ca.shared.global [%0], [%1], 16;\n"
               :: "r"(smem_dst), "l"(gsrc));
}

// QK: f16 inputs, f16 accumulate (D/C packed f16x2 -> 2 regs)
__device__ __forceinline__ void mma_f16acc(uint32_t d[2], const uint32_t a[4],
                                           uint32_t b0, uint32_t b1) {
  asm volatile("mma.sync.aligned.m16n8k16.row.col.f16.f16.f16.f16 "
               "{%0,%1}, {%2,%3,%4,%5}, {%6,%7}, {%0,%1};"
               : "+r"(d[0]), "+r"(d[1])
               : "r"(a[0]), "r"(a[1]), "r"(a[2]), "r"(a[3]), "r"(b0), "r"(b1));
}

// PV: f16 inputs, f32 accumulate
__device__ __forceinline__ void mma_f32acc(float d[4], const uint32_t a[4],
                                           uint32_t b0, uint32_t b1) {
  asm volatile("mma.sync.aligned.m16n8k16.row.col.f32.f16.f16.f32 "
               "{%0,%1,%2,%3}, {%4,%5,%6,%7}, {%8,%9}, {%0,%1,%2,%3};"
               : "+f"(d[0]), "+f"(d[1]), "+f"(d[2]), "+f"(d[3])
               : "r"(a[0]), "r"(a[1]), "r"(a[2]), "r"(a[3]), "r"(b0), "r"(b1));
}

__device__ __forceinline__ void prefetch_kv(uint32_t sbase, int b, int jt, int stage, int tid) {
  uint32_t st = sbase + (uint32_t)stage * STAGE_BYTES;
  const __half* Ksrc = g_Kh + ((size_t)b*HWN + jt*64)*64;
  const __half* Vsrc = g_Vh + (size_t)b*64*HWN + jt*64;
  #pragma unroll
  for (int k = 0; k < 4; k++) {
    int i = tid + k*256;             // 0..1023
    if (i < 512) {                   // K tile: 64 rows x 128B
      int r = i >> 3, c = i & 7;
      cp_async16(st + (uint32_t)(r*KVW*4 + c*16), Ksrc + r*64 + c*8);
    } else {                         // V tile (transposed): 64 d-rows x 128B
      int j = i - 512, r = j >> 3, c = j & 7;
      cp_async16(st + KBYTES + (uint32_t)(r*KVW*4 + c*16), Vsrc + (size_t)r*HWN + c*8);
    }
  }
}

__global__ void __launch_bounds__(256, 2) attn_kernel() {
  extern __shared__ float sh[];
  uint32_t sbase = (uint32_t)__cvta_generic_to_shared(sh);
  const int b = blockIdx.y, m0 = blockIdx.x*128;
  const int tid = threadIdx.x, w = tid >> 5, lane = tid & 31;
  const int g = lane >> 2, t = lane & 3;

  // Q fragments (f16x2 words), resident in registers
  const uint32_t* Qu = (const uint32_t*)g_Qh + ((size_t)b*HWN + m0 + w*16)*32;
  uint32_t qa[4][4];
  #pragma unroll
  for (int kt = 0; kt < 4; kt++) {
    qa[kt][0] = Qu[ g   *32 + kt*8 + t    ];
    qa[kt][1] = Qu[(g+8)*32 + kt*8 + t    ];
    qa[kt][2] = Qu[ g   *32 + kt*8 + t + 4];
    qa[kt][3] = Qu[(g+8)*32 + kt*8 + t + 4];
  }

  float m0r = -1e30f, m1r = -1e30f, l0 = 0.f, l1 = 0.f;
  float o[8][4] = {};

  prefetch_kv(sbase, b, 0, 0, tid);
  asm volatile("cp.async.commit_group;\n" ::: "memory");

  for (int jt = 0; jt < 64; jt++) {
    if (jt + 1 < 64) {
      prefetch_kv(sbase, b, jt+1, (jt+1)&1, tid);
      asm volatile("cp.async.commit_group;\n" ::: "memory");
      asm volatile("cp.async.wait_group 1;\n" ::: "memory");
    } else {
      asm volatile("cp.async.wait_group 0;\n" ::: "memory");
    }
    __syncthreads();

    const uint32_t* Ku32 = (const uint32_t*)sh + (jt&1)*(STAGE_BYTES/4);
    const uint32_t* Vu32 = Ku32 + KBYTES/4;

    // ---- S = Q K^T (16x64 per warp), f16 accumulate ----
    uint32_t sd[8][2];
    #pragma unroll
    for (int nt = 0; nt < 8; nt++) { sd[nt][0] = 0u; sd[nt][1] = 0u; }
    #pragma unroll
    for (int kt = 0; kt < 4; kt++) {
      #pragma unroll
      for (int nt = 0; nt < 8; nt++) {
        uint32_t b0 = Ku32[(nt*8 + g)*KVW + kt*8 + t];
        uint32_t b1 = Ku32[(nt*8 + g)*KVW + kt*8 + t + 4];
        mma_f16acc(sd[nt], qa[kt], b0, b1);
      }
    }
    // unpack to f32
    float s[8][4];
    #pragma unroll
    for (int nt = 0; nt < 8; nt++) {
      float2 v0 = __half22float2(*(const __half2*)&sd[nt][0]);
      float2 v1 = __half22float2(*(const __half2*)&sd[nt][1]);
      s[nt][0] = v0.x; s[nt][1] = v0.y; s[nt][2] = v1.x; s[nt][3] = v1.y;
    }

    // ---- online softmax (rows g and g+8) ----
    float rmax0 = -1e30f, rmax1 = -1e30f;
    #pragma unroll
    for (int nt = 0; nt < 8; nt++) {
      rmax0 = fmaxf(rmax0, fmaxf(s[nt][0], s[nt][1]));
      rmax1 = fmaxf(rmax1, fmaxf(s[nt][2], s[nt][3]));
    }
    rmax0 = fmaxf(rmax0, __shfl_xor_sync(0xffffffffu, rmax0, 1));
    rmax0 = fmaxf(rmax0, __shfl_xor_sync(0xffffffffu, rmax0, 2));
    rmax1 = fmaxf(rmax1, __shfl_xor_sync(0xffffffffu, rmax1, 1));
    rmax1 = fmaxf(rmax1, __shfl_xor_sync(0xffffffffu, rmax1, 2));
    float mn0 = fmaxf(m0r, rmax0), mn1 = fmaxf(m1r, rmax1);
    float c0 = __expf(m0r - mn0), c1 = __expf(m1r - mn1);
    m0r = mn0; m1r = mn1;
    float rs0 = 0.f, rs1 = 0.f;
    #pragma unroll
    for (int nt = 0; nt < 8; nt++) {
      s[nt][0] = __expf(s[nt][0] - mn0);
      s[nt][1] = __expf(s[nt][1] - mn0);
      s[nt][2] = __expf(s[nt][2] - mn1);
      s[nt][3] = __expf(s[nt][3] - mn1);
      rs0 += s[nt][0] + s[nt][1];
      rs1 += s[nt][2] + s[nt][3];
    }
    rs0 += __shfl_xor_sync(0xffffffffu, rs0, 1);
    rs0 += __shfl_xor_sync(0xffffffffu, rs0, 2);
    rs1 += __shfl_xor_sync(0xffffffffu, rs1, 1);
    rs1 += __shfl_xor_sync(0xffffffffu, rs1, 2);
    l0 = l0*c0 + rs0;  l1 = l1*c1 + rs1;
    #pragma unroll
    for (int nt = 0; nt < 8; nt++) {
      o[nt][0] *= c0; o[nt][1] *= c0; o[nt][2] *= c1; o[nt][3] *= c1;
    }

    // ---- O += P V : C-frag layout == A-frag layout (no shuffles) ----
    #pragma unroll
    for (int kt = 0; kt < 4; kt++) {
      uint32_t pa[4];
      pa[0] = pack_f16x2(s[2*kt  ][0], s[2*kt  ][1]);
      pa[1] = pack_f16x2(s[2*kt  ][2], s[2*kt  ][3]);
      pa[2] = pack_f16x2(s[2*kt+1][0], s[2*kt+1][1]);
      pa[3] = pack_f16x2(s[2*kt+1][2], s[2*kt+1][3]);
      #pragma unroll
      for (int nt = 0; nt < 8; nt++) {
        uint32_t b0 = Vu32[(nt*8 + g)*KVW + kt*8 + t];
        uint32_t b1 = Vu32[(nt*8 + g)*KVW + kt*8 + t + 4];
        mma_f32acc(o[nt], pa, b0, b1);
      }
    }
    __syncthreads();   // all reads of this stage done before refill
  }

  float* AO = g_AO + ((size_t)b*HWN + m0 + w*16)*64;
  float i0 = 1.f / l0, i1 = 1.f / l1;
  #pragma unroll
  for (int nt = 0; nt < 8; nt++) {
    *(float2*)&AO[ g   *64 + nt*8 + 2*t] = make_float2(o[nt][0]*i0, o[nt][1]*i0);
    *(float2*)&AO[(g+8)*64 + nt*8 + 2*t] = make_float2(o[nt][2]*i1, o[nt][3]*i1);
  }
}

// ===================================================================
// Kernel 3: out-proj + gate MLP + sigmoid  (attn_out -> g_SW)
// ===================================================================
__global__ void proj_kernel(const float* __restrict__ ow_, const float* __restrict__ ob,
                            const float* __restrict__ g1w, const float* __restrict__ g1b,
                            const float* __restrict__ g2w, const float* __restrict__ g2b) {
  extern __shared__ float sh[];
  float* owt  = sh;              // [64][128]
  float* g1wt = owt + 8192;      // [128][32]
  float* g2wt = g1wt + 4096;     // [32][128]
  float* obs  = g2wt + 4096;     // 128
  float* g1bs = obs + 128;       // 32
  float* g2bs = g1bs + 32;       // 128
  float* ao   = g2bs + 128;      // [32][64]
  float* gf2  = ao + 2048;       // [32][128]
  float* hb   = gf2 + 4096;      // [32][32]
  float* swt  = hb + 1024;       // [128][32]
  const int b = blockIdx.y, p0 = blockIdx.x*32, tid = threadIdx.x;

  for (int i = tid; i < 8192; i += 256) { int ci = i>>6, d = i&63;  owt [d*128+ci] = ow_[i]; }
  for (int i = tid; i < 4096; i += 256) { int co = i>>7, c = i&127; g1wt[c*32 +co] = g1w[i]; }
  for (int i = tid; i < 4096; i += 256) { int ci = i>>5, c = i&31;  g2wt[c*128+ci] = g2w[i]; }
  for (int i = tid; i < 128;  i += 256) obs[i]  = ob[i];
  for (int i = tid; i < 32;   i += 256) g1bs[i] = g1b[i];
  for (int i = tid; i < 128;  i += 256) g2bs[i] = g2b[i];
  const float* AOg = g_AO + ((size_t)b*HWN + p0)*64;
  for (int i = tid; i < 2048; i += 256) ao[i] = AOg[i];
  __syncthreads();

  for (int o = tid; o < 4096; o += 256) {
    int p = o >> 7, ci = o & 127;
    float s = obs[ci];
    const float* av = &ao[p*64];
    #pragma unroll 8
    for (int d = 0; d < 64; d++) s += owt[d*128+ci]*av[d];
    gf2[o] = s;
  }
  __syncthreads();
  for (int o = tid; o < 1024; o += 256) {
    int p = o >> 5, co = o & 31;
    float s = g1bs[co];
    const float* gv = &gf2[p*128];
    #pragma unroll 8
    for (int c = 0; c < 128; c++) s += g1wt[c*32+co]*gv[c];
    hb[o] = fmaxf(s, 0.f);
  }
  __syncthreads();
  for (int o = tid; o < 4096; o += 256) {
    int p = o >> 7, ci = o & 127;
    float s = g2bs[ci];
    const float* hv = &hb[p*32];
    #pragma unroll
    for (int c = 0; c < 32; c++) s += g2wt[c*128+ci]*hv[c];
    swt[ci*32 + p] = 1.f/(1.f + __expf(-s));
  }
  __syncthreads();
  for (int o = tid; o < 4096; o += 256) {
    int ci = o >> 5, pp = o & 31;
    g_SW[((size_t)b*128+ci)*HWN + p0 + pp] = swt[o];
  }
}

// ===================================================================
// Kernel 4: final gating (with bilinear resample of gates for x2..x4)
// ===================================================================
__device__ __forceinline__ float sample_sw(const float* __restrict__ plane, int y, int x, int OH) {
  float fy = (float)y * 63.0f / (float)(OH-1);
  float fx = (float)x * 63.0f / (float)(OH-1);
  int y0 = (int)fy; if (y0 > 63) y0 = 63;
  int x0 = (int)fx; if (x0 > 63) x0 = 63;
  int y1 = min(y0+1, 63), x1 = min(x0+1, 63);
  float wy = fy - (float)y0, wx = fx - (float)x0;
  float a = plane[y0*64+x0], bv = plane[y0*64+x1];
  float c = plane[y1*64+x0], d = plane[y1*64+x1];
  return (a*(1.f-wx)+bv*wx)*(1.f-wy) + (c*(1.f-wx)+d*wx)*wy;
}

__global__ void gate_kernel(const float* __restrict__ x1, const float* __restrict__ x2,
                            const float* __restrict__ x3, const float* __restrict__ x4,
                            float* __restrict__ out) {
  int idx = blockIdx.x*256 + threadIdx.x;
  const int N1 = BB*32*4096, N2 = BB*32*1024, N3 = BB*32*256, N4 = BB*32*64;
  if (idx < N1) {
    int b = idx >> 17, c = (idx >> 12) & 31, p = idx & 4095;
    out[idx] = x1[idx]*(1.f + g_SW[((size_t)b*128 + c)*HWN + p]);
  } else if (idx < N1+N2) {
    int i = idx - N1;
    int b = i >> 15, c = (i >> 10) & 31, y = (i >> 5) & 31, x = i & 31;
    const float* plane = g_SW + ((size_t)b*128 + 32 + c)*HWN;
    out[idx] = x2[i]*(1.f + sample_sw(plane, y, x, 32));
  } else if (idx < N1+N2+N3) {
    int i = idx - N1 - N2;
    int b = i >> 13, c = (i >> 8) & 31, y = (i >> 4) & 15, x = i & 15;
    const float* plane = g_SW + ((size_t)b*128 + 64 + c)*HWN;
    out[idx] = x3[i]*(1.f + sample_sw(plane, y, x, 16));
  } else if (idx < N1+N2+N3+N4) {
    int i = idx - N1 - N2 - N3;
    int b = i >> 11, c = (i >> 6) & 31, y = (i >> 3) & 7, x = i & 7;
    const float* plane = g_SW + ((size_t)b*128 + 96 + c)*HWN;
    out[idx] = x4[i]*(1.f + sample_sw(plane, y, x, 8));
  }
}

// ===================================================================
extern "C" void kernel_launch(void* const* d_in, const int* in_sizes, int n_in,
                              void* d_out, int out_size) {
  const float* x1  = (const float*)d_in[0];
  const float* x2  = (const float*)d_in[1];
  const float* x3  = (const float*)d_in[2];
  const float* x4  = (const float*)d_in[3];
  const float* qw  = (const float*)d_in[4];
  const float* qb  = (const float*)d_in[5];
  const float* kw  = (const float*)d_in[6];
  const float* kb  = (const float*)d_in[7];
  const float* vw  = (const float*)d_in[8];
  const float* vb  = (const float*)d_in[9];
  const float* ow_ = (const float*)d_in[10];
  const float* ob  = (const float*)d_in[11];
  const float* g1w = (const float*)d_in[12];
  const float* g1b = (const float*)d_in[13];
  const float* g2w = (const float*)d_in[14];
  const float* g2b = (const float*)d_in[15];
  float* out = (float*)d_out;

  const int QKV_SMEM  = (128*192 + 128*68 + 192 + 192*65) * 4;  // 183808 B
  const int ATTN_SMEM = STAGE_BYTES*2;                          // 36864 B
  const int PROJ_SMEM = (8192+4096+4096+128+32+128+2048+4096+1024+4096) * 4; // 111360 B

  cudaFuncSetAttribute(qkv_kernel,  cudaFuncAttributeMaxDynamicSharedMemorySize, QKV_SMEM);
  cudaFuncSetAttribute(attn_kernel, cudaFuncAttributeMaxDynamicSharedMemorySize, ATTN_SMEM);
  cudaFuncSetAttribute(proj_kernel, cudaFuncAttributeMaxDynamicSharedMemorySize, PROJ_SMEM);

  qkv_kernel <<<dim3(64, BB),  256, QKV_SMEM >>>(x1, x2, x3, x4, qw, qb, kw, kb, vw, vb);
  attn_kernel<<<dim3(32, BB),  256, ATTN_SMEM>>>();
  proj_kernel<<<dim3(128, BB), 256, PROJ_SMEM>>>(ow_, ob, g1w, g1b, g2w, g2b);

  const int TOTAL = BB*32*(4096 + 1024 + 256 + 64);  // 1392640
  gate_kernel<<<(TOTAL + 255)/256, 256>>>(x1, x2, x3, x4, out);
}

// round 7
// speedup vs baseline: 1.2949x; 1.1906x over previous
#include <cuda_runtime.h>
#include <cuda_fp16.h>
#include <math.h>
#include <stdint.h>

#define BB 8
#define HWN 4096

// -------- scratch (allocation-free rule: __device__ globals) --------
__device__ __half g_Qh[BB*HWN*64];   // [b][p][ci]
__device__ __half g_Kh[BB*HWN*64];   // [b][p][ci]
__device__ __half g_Vh[BB*64*HWN];   // [b][ci][p]  (transposed)
__device__ float g_AO[BB*HWN*64];    // attention output [b][p][d]
__device__ float g_SW[BB*128*HWN];   // sigmoid gates [b][ci][p]

__device__ __forceinline__ uint32_t pack_f16x2(float lo, float hi) {
  uint32_t r;
  asm("cvt.rn.f16x2.f32 %0, %1, %2;" : "=r"(r) : "f"(hi), "f"(lo));
  return r;
}

// PV / generic: f16 inputs, f32 accumulate
__device__ __forceinline__ void mma_f32acc(float d[4], const uint32_t a[4],
                                           uint32_t b0, uint32_t b1) {
  asm volatile("mma.sync.aligned.m16n8k16.row.col.f32.f16.f16.f32 "
               "{%0,%1,%2,%3}, {%4,%5,%6,%7}, {%8,%9}, {%0,%1,%2,%3};"
               : "+f"(d[0]), "+f"(d[1]), "+f"(d[2]), "+f"(d[3])
               : "r"(a[0]), "r"(a[1]), "r"(a[2]), "r"(a[3]), "r"(b0), "r"(b1));
}
// QK: f16 inputs, f16 accumulate (D/C packed f16x2 -> 2 regs)
__device__ __forceinline__ void mma_f16acc(uint32_t d[2], const uint32_t a[4],
                                           uint32_t b0, uint32_t b1) {
  asm volatile("mma.sync.aligned.m16n8k16.row.col.f16.f16.f16.f16 "
               "{%0,%1}, {%2,%3,%4,%5}, {%6,%7}, {%0,%1};"
               : "+r"(d[0]), "+r"(d[1])
               : "r"(a[0]), "r"(a[1]), "r"(a[2]), "r"(a[3]), "r"(b0), "r"(b1));
}

// ===================================================================
// Kernel 1: fused gf-build (upsample+concat) + QKV 1x1 convs (tensor)
// grid (64 rows, B), 384 threads (12 warps; warp w owns out-rows 16w..16w+15)
// ===================================================================
// smem (floats): gfs[128][68] | gf16 u32[64][68] | W16 u32[192][68]
//                | bias[192] | outs[192][66]
#define QO_GFS   0
#define QO_GF16  (QO_GFS + 128*68)
#define QO_W16   (QO_GF16 + 64*68)
#define QO_BIAS  (QO_W16 + 192*68)
#define QO_OUTS  (QO_BIAS + 192)
#define QKV_FLOATS (QO_OUTS + 192*66)

__global__ void __launch_bounds__(384) qkv_kernel(
    const float* __restrict__ x1, const float* __restrict__ x2,
    const float* __restrict__ x3, const float* __restrict__ x4,
    const float* __restrict__ qw, const float* __restrict__ qb,
    const float* __restrict__ kw, const float* __restrict__ kb,
    const float* __restrict__ vw, const float* __restrict__ vb) {
  extern __shared__ float sh[];
  float*    gfs  = sh + QO_GFS;
  uint32_t* gf16 = (uint32_t*)(sh + QO_GF16);
  uint32_t* W16  = (uint32_t*)(sh + QO_W16);
  float*    bias = sh + QO_BIAS;
  float*    outs = sh + QO_OUTS;
  const int b = blockIdx.y, y = blockIdx.x, tid = threadIdx.x;

  // ---- weights -> f16 A-tiles (row = out-channel, word = k-pair) ----
  for (int i = tid; i < 192*64; i += 384) {
    int r = i >> 6, wd = i & 63;
    const float* src = (r < 64) ? (qw + r*128) : (r < 128 ? kw + (r-64)*128 : vw + (r-128)*128);
    W16[r*68 + wd] = pack_f16x2(src[2*wd], src[2*wd+1]);
  }
  for (int i = tid; i < 192; i += 384)
    bias[i] = (i < 64) ? qb[i] : (i < 128 ? kb[i-64] : vb[i-128]);

  // ---- gf build (channel-major f32) ----
  for (int i = tid; i < 32*64; i += 384) {
    int c = i >> 6, x = i & 63;
    gfs[c*68 + x] = x1[((b*32 + c)*64 + y)*64 + x];
  }
  const float* srcs[3] = {x2, x3, x4};
  const int    Hs[3]   = {32, 16, 8};
  #pragma unroll
  for (int lvl = 0; lvl < 3; lvl++) {
    const int H = Hs[lvl];
    const float* src = srcs[lvl];
    float fy = (float)y * (float)(H-1) / 63.0f;
    int y0 = (int)fy; if (y0 > H-1) y0 = H-1;
    int y1i = min(y0+1, H-1);
    float wy = fy - (float)y0;
    for (int i = tid; i < 32*64; i += 384) {
      int c = i >> 6, x = i & 63;
      float fx = (float)x * (float)(H-1) / 63.0f;
      int x0 = (int)fx; if (x0 > H-1) x0 = H-1;
      int x1i = min(x0+1, H-1);
      float wx = fx - (float)x0;
      const float* r0 = src + ((b*32 + c)*H + y0)*H;
      const float* r1 = src + ((b*32 + c)*H + y1i)*H;
      float top = r0[x0]*(1.f-wx) + r0[x1i]*wx;
      float bot = r1[x0]*(1.f-wx) + r1[x1i]*wx;
      gfs[(32*(lvl+1) + c)*68 + x] = top*(1.f-wy) + bot*wy;
    }
  }
  __syncthreads();

  // ---- pack gf -> f16 B-tile (row = position, word = k-pair) ----
  for (int i = tid; i < 64*64; i += 384) {
    int x = i >> 6, cw = i & 63;
    gf16[x*68 + cw] = pack_f16x2(gfs[(2*cw)*68 + x], gfs[(2*cw+1)*68 + x]);
  }
  __syncthreads();

  // ---- tensor GEMM: [192 out] x [64 pos], K=128 ----
  {
    const int w = tid >> 5, lane = tid & 31;
    const int g = lane >> 2, t = lane & 3;
    uint32_t qa[8][4];
    #pragma unroll
    for (int kt = 0; kt < 8; kt++) {
      qa[kt][0] = W16[(16*w + g    )*68 + kt*8 + t];
      qa[kt][1] = W16[(16*w + g + 8)*68 + kt*8 + t];
      qa[kt][2] = W16[(16*w + g    )*68 + kt*8 + t + 4];
      qa[kt][3] = W16[(16*w + g + 8)*68 + kt*8 + t + 4];
    }
    float acc[8][4];
    #pragma unroll
    for (int nt = 0; nt < 8; nt++) { acc[nt][0]=acc[nt][1]=acc[nt][2]=acc[nt][3]=0.f; }
    #pragma unroll
    for (int kt = 0; kt < 8; kt++) {
      #pragma unroll
      for (int nt = 0; nt < 8; nt++) {
        uint32_t b0 = gf16[(8*nt + g)*68 + kt*8 + t];
        uint32_t b1 = gf16[(8*nt + g)*68 + kt*8 + t + 4];
        mma_f32acc(acc[nt], qa[kt], b0, b1);
      }
    }
    float bv0 = bias[16*w + g], bv1 = bias[16*w + g + 8];
    #pragma unroll
    for (int nt = 0; nt < 8; nt++) {
      *(float2*)&outs[(16*w + g    )*66 + 8*nt + 2*t] = make_float2(acc[nt][0]+bv0, acc[nt][1]+bv0);
      *(float2*)&outs[(16*w + g + 8)*66 + 8*nt + 2*t] = make_float2(acc[nt][2]+bv1, acc[nt][3]+bv1);
    }
  }
  __syncthreads();

  // ---- writeout: Q,K f16 [p][64]; V f16 transposed [d][p] ----
  const int pbase = b*HWN + y*64;
  uint32_t* Qu = (uint32_t*)g_Qh + (size_t)pbase*32;
  uint32_t* Ku = (uint32_t*)g_Kh + (size_t)pbase*32;
  for (int i = tid; i < 2048; i += 384) {
    int p = i >> 5, c2 = i & 31;
    Qu[p*32 + c2] = pack_f16x2(outs[(2*c2)*66 + p],     outs[(2*c2+1)*66 + p]);
    Ku[p*32 + c2] = pack_f16x2(outs[(64+2*c2)*66 + p],  outs[(65+2*c2)*66 + p]);
  }
  uint32_t* Vu = (uint32_t*)g_Vh;
  for (int i = tid; i < 2048; i += 384) {
    int d = i >> 5, px = i & 31;
    const float* vr = &outs[(128+d)*66];
    Vu[((size_t)(b*64+d)*HWN + y*64)/2 + px] = pack_f16x2(vr[2*px], vr[2*px+1]);
  }
}

// ===================================================================
// Kernel 2: f16 tensor-core flash attention, half2 softmax
// grid (32 q-tiles of 128, B), 256 threads (8 warps x 16 rows), 2 CTA/SM
// ===================================================================
#define KVW 36                       // row stride in u32 (72 halves)
#define KBYTES (64*KVW*4)            // 9216 B per tile
#define STAGE_BYTES (2*KBYTES)       // K + V = 18432 B

__device__ __forceinline__ void cp_async16(uint32_t smem_dst, const void* gsrc) {
  asm volatile("cp.async.ca.shared.global [%0], [%1], 16;\n"
               :: "r"(smem_dst), "l"(gsrc));
}

__device__ __forceinline__ void prefetch_kv(uint32_t sbase, int b, int jt, int stage, int tid) {
  uint32_t st = sbase + (uint32_t)stage * STAGE_BYTES;
  const __half* Ksrc = g_Kh + ((size_t)b*HWN + jt*64)*64;
  const __half* Vsrc = g_Vh + (size_t)b*64*HWN + jt*64;
  #pragma unroll
  for (int k = 0; k < 4; k++) {
    int i = tid + k*256;             // 0..1023
    if (i < 512) {                   // K tile: 64 rows x 128B
      int r = i >> 3, c = i & 7;
      cp_async16(st + (uint32_t)(r*KVW*4 + c*16), Ksrc + r*64 + c*8);
    } else {                         // V tile (transposed): 64 d-rows x 128B
      int j = i - 512, r = j >> 3, c = j & 7;
      cp_async16(st + KBYTES + (uint32_t)(r*KVW*4 + c*16), Vsrc + (size_t)r*HWN + c*8);
    }
  }
}

__global__ void __launch_bounds__(256, 2) attn_kernel() {
  extern __shared__ float sh[];
  uint32_t sbase = (uint32_t)__cvta_generic_to_shared(sh);
  const int b = blockIdx.y, m0 = blockIdx.x*128;
  const int tid = threadIdx.x, w = tid >> 5, lane = tid & 31;
  const int g = lane >> 2, t = lane & 3;

  const uint32_t* Qu = (const uint32_t*)g_Qh + ((size_t)b*HWN + m0 + w*16)*32;
  uint32_t qa[4][4];
  #pragma unroll
  for (int kt = 0; kt < 4; kt++) {
    qa[kt][0] = Qu[ g   *32 + kt*8 + t    ];
    qa[kt][1] = Qu[(g+8)*32 + kt*8 + t    ];
    qa[kt][2] = Qu[ g   *32 + kt*8 + t + 4];
    qa[kt][3] = Qu[(g+8)*32 + kt*8 + t + 4];
  }

  float m0r = -1e30f, m1r = -1e30f, l0 = 0.f, l1 = 0.f;
  float o[8][4] = {};
  const __half2 l2e2 = __float2half2_rn(1.44269504f);

  prefetch_kv(sbase, b, 0, 0, tid);
  asm volatile("cp.async.commit_group;\n" ::: "memory");

  for (int jt = 0; jt < 64; jt++) {
    if (jt + 1 < 64) {
      prefetch_kv(sbase, b, jt+1, (jt+1)&1, tid);
      asm volatile("cp.async.commit_group;\n" ::: "memory");
      asm volatile("cp.async.wait_group 1;\n" ::: "memory");
    } else {
      asm volatile("cp.async.wait_group 0;\n" ::: "memory");
    }
    __syncthreads();

    const uint32_t* Ku32 = (const uint32_t*)sh + (jt&1)*(STAGE_BYTES/4);
    const uint32_t* Vu32 = Ku32 + KBYTES/4;

    // ---- S = Q K^T (16x64 per warp), f16 accumulate ----
    uint32_t sd[8][2];
    #pragma unroll
    for (int nt = 0; nt < 8; nt++) { sd[nt][0] = 0u; sd[nt][1] = 0u; }
    #pragma unroll
    for (int kt = 0; kt < 4; kt++) {
      #pragma unroll
      for (int nt = 0; nt < 8; nt++) {
        uint32_t b0 = Ku32[(nt*8 + g)*KVW + kt*8 + t];
        uint32_t b1 = Ku32[(nt*8 + g)*KVW + kt*8 + t + 4];
        mma_f16acc(sd[nt], qa[kt], b0, b1);
      }
    }

    // ---- half2 softmax: max, exp2 in f16x2, P stays packed ----
    __half2 hm0 = *(__half2*)&sd[0][0];
    __half2 hm1 = *(__half2*)&sd[0][1];
    #pragma unroll
    for (int nt = 1; nt < 8; nt++) {
      hm0 = __hmax2(hm0, *(__half2*)&sd[nt][0]);
      hm1 = __hmax2(hm1, *(__half2*)&sd[nt][1]);
    }
    float rmax0 = fmaxf(__low2float(hm0), __high2float(hm0));
    float rmax1 = fmaxf(__low2float(hm1), __high2float(hm1));
    rmax0 = fmaxf(rmax0, __shfl_xor_sync(0xffffffffu, rmax0, 1));
    rmax0 = fmaxf(rmax0, __shfl_xor_sync(0xffffffffu, rmax0, 2));
    rmax1 = fmaxf(rmax1, __shfl_xor_sync(0xffffffffu, rmax1, 1));
    rmax1 = fmaxf(rmax1, __shfl_xor_sync(0xffffffffu, rmax1, 2));
    float mn0 = fmaxf(m0r, rmax0), mn1 = fmaxf(m1r, rmax1);
    float c0 = __expf(m0r - mn0), c1 = __expf(m1r - mn1);
    m0r = mn0; m1r = mn1;

    __half2 off0 = __float2half2_rn(-mn0 * 1.44269504f);
    __half2 off1 = __float2half2_rn(-mn1 * 1.44269504f);
    uint32_t pe[8][2];
    #pragma unroll
    for (int nt = 0; nt < 8; nt++) {
      __half2 x0 = __hfma2(*(__half2*)&sd[nt][0], l2e2, off0);
      __half2 x1 = __hfma2(*(__half2*)&sd[nt][1], l2e2, off1);
      asm("ex2.approx.f16x2 %0, %1;" : "=r"(pe[nt][0]) : "r"(*(uint32_t*)&x0));
      asm("ex2.approx.f16x2 %0, %1;" : "=r"(pe[nt][1]) : "r"(*(uint32_t*)&x1));
    }
    __half2 sum0 = *(__half2*)&pe[0][0];
    __half2 sum1 = *(__half2*)&pe[0][1];
    #pragma unroll
    for (int nt = 1; nt < 8; nt++) {
      sum0 = __hadd2(sum0, *(__half2*)&pe[nt][0]);
      sum1 = __hadd2(sum1, *(__half2*)&pe[nt][1]);
    }
    float2 f0 = __half22float2(sum0), f1 = __half22float2(sum1);
    float rs0 = f0.x + f0.y, rs1 = f1.x + f1.y;
    rs0 += __shfl_xor_sync(0xffffffffu, rs0, 1);
    rs0 += __shfl_xor_sync(0xffffffffu, rs0, 2);
    rs1 += __shfl_xor_sync(0xffffffffu, rs1, 1);
    rs1 += __shfl_xor_sync(0xffffffffu, rs1, 2);
    l0 = l0*c0 + rs0;  l1 = l1*c1 + rs1;
    #pragma unroll
    for (int nt = 0; nt < 8; nt++) {
      o[nt][0] *= c0; o[nt][1] *= c0; o[nt][2] *= c1; o[nt][3] *= c1;
    }

    // ---- O += P V : pe IS the packed A-frag (no shuffles, no repack) ----
    #pragma unroll
    for (int kt = 0; kt < 4; kt++) {
      uint32_t pa[4] = { pe[2*kt][0], pe[2*kt][1], pe[2*kt+1][0], pe[2*kt+1][1] };
      #pragma unroll
      for (int nt = 0; nt < 8; nt++) {
        uint32_t b0 = Vu32[(nt*8 + g)*KVW + kt*8 + t];
        uint32_t b1 = Vu32[(nt*8 + g)*KVW + kt*8 + t + 4];
        mma_f32acc(o[nt], pa, b0, b1);
      }
    }
    __syncthreads();   // all reads of this stage done before refill
  }

  float* AO = g_AO + ((size_t)b*HWN + m0 + w*16)*64;
  float i0 = 1.f / l0, i1 = 1.f / l1;
  #pragma unroll
  for (int nt = 0; nt < 8; nt++) {
    *(float2*)&AO[ g   *64 + nt*8 + 2*t] = make_float2(o[nt][0]*i0, o[nt][1]*i0);
    *(float2*)&AO[(g+8)*64 + nt*8 + 2*t] = make_float2(o[nt][2]*i1, o[nt][3]*i1);
  }
}

// ===================================================================
// Kernel 3: out-proj + gate MLP + sigmoid  (attn_out -> g_SW)
// ===================================================================
__global__ void proj_kernel(const float* __restrict__ ow_, const float* __restrict__ ob,
                            const float* __restrict__ g1w, const float* __restrict__ g1b,
                            const float* __restrict__ g2w, const float* __restrict__ g2b) {
  extern __shared__ float sh[];
  float* owt  = sh;              // [64][128]
  float* g1wt = owt + 8192;      // [128][32]
  float* g2wt = g1wt + 4096;     // [32][128]
  float* obs  = g2wt + 4096;     // 128
  float* g1bs = obs + 128;       // 32
  float* g2bs = g1bs + 32;       // 128
  float* ao   = g2bs + 128;      // [32][64]
  float* gf2  = ao + 2048;       // [32][128]
  float* hb   = gf2 + 4096;      // [32][32]
  float* swt  = hb + 1024;       // [128][32]
  const int b = blockIdx.y, p0 = blockIdx.x*32, tid = threadIdx.x;

  for (int i = tid; i < 8192; i += 256) { int ci = i>>6, d = i&63;  owt [d*128+ci] = ow_[i]; }
  for (int i = tid; i < 4096; i += 256) { int co = i>>7, c = i&127; g1wt[c*32 +co] = g1w[i]; }
  for (int i = tid; i < 4096; i += 256) { int ci = i>>5, c = i&31;  g2wt[c*128+ci] = g2w[i]; }
  for (int i = tid; i < 128;  i += 256) obs[i]  = ob[i];
  for (int i = tid; i < 32;   i += 256) g1bs[i] = g1b[i];
  for (int i = tid; i < 128;  i += 256) g2bs[i] = g2b[i];
  const float* AOg = g_AO + ((size_t)b*HWN + p0)*64;
  for (int i = tid; i < 2048; i += 256) ao[i] = AOg[i];
  __syncthreads();

  for (int o = tid; o < 4096; o += 256) {
    int p = o >> 7, ci = o & 127;
    float s = obs[ci];
    const float* av = &ao[p*64];
    #pragma unroll 8
    for (int d = 0; d < 64; d++) s += owt[d*128+ci]*av[d];
    gf2[o] = s;
  }
  __syncthreads();
  for (int o = tid; o < 1024; o += 256) {
    int p = o >> 5, co = o & 31;
    float s = g1bs[co];
    const float* gv = &gf2[p*128];
    #pragma unroll 8
    for (int c = 0; c < 128; c++) s += g1wt[c*32+co]*gv[c];
    hb[o] = fmaxf(s, 0.f);
  }
  __syncthreads();
  for (int o = tid; o < 4096; o += 256) {
    int p = o >> 7, ci = o & 127;
    float s = g2bs[ci];
    const float* hv = &hb[p*32];
    #pragma unroll
    for (int c = 0; c < 32; c++) s += g2wt[c*128+ci]*hv[c];
    swt[ci*32 + p] = 1.f/(1.f + __expf(-s));
  }
  __syncthreads();
  for (int o = tid; o < 4096; o += 256) {
    int ci = o >> 5, pp = o & 31;
    g_SW[((size_t)b*128+ci)*HWN + p0 + pp] = swt[o];
  }
}

// ===================================================================
// Kernel 4: final gating (with bilinear resample of gates for x2..x4)
// ===================================================================
__device__ __forceinline__ float sample_sw(const float* __restrict__ plane, int y, int x, int OH) {
  float fy = (float)y * 63.0f / (float)(OH-1);
  float fx = (float)x * 63.0f / (float)(OH-1);
  int y0 = (int)fy; if (y0 > 63) y0 = 63;
  int x0 = (int)fx; if (x0 > 63) x0 = 63;
  int y1 = min(y0+1, 63), x1 = min(x0+1, 63);
  float wy = fy - (float)y0, wx = fx - (float)x0;
  float a = plane[y0*64+x0], bv = plane[y0*64+x1];
  float c = plane[y1*64+x0], d = plane[y1*64+x1];
  return (a*(1.f-wx)+bv*wx)*(1.f-wy) + (c*(1.f-wx)+d*wx)*wy;
}

__global__ void gate_kernel(const float* __restrict__ x1, const float* __restrict__ x2,
                            const float* __restrict__ x3, const float* __restrict__ x4,
                            float* __restrict__ out) {
  int idx = blockIdx.x*256 + threadIdx.x;
  const int N1 = BB*32*4096, N2 = BB*32*1024, N3 = BB*32*256, N4 = BB*32*64;
  if (idx < N1) {
    int b = idx >> 17, c = (idx >> 12) & 31, p = idx & 4095;
    out[idx] = x1[idx]*(1.f + g_SW[((size_t)b*128 + c)*HWN + p]);
  } else if (idx < N1+N2) {
    int i = idx - N1;
    int b = i >> 15, c = (i >> 10) & 31, y = (i >> 5) & 31, x = i & 31;
    const float* plane = g_SW + ((size_t)b*128 + 32 + c)*HWN;
    out[idx] = x2[i]*(1.f + sample_sw(plane, y, x, 32));
  } else if (idx < N1+N2+N3) {
    int i = idx - N1 - N2;
    int b = i >> 13, c = (i >> 8) & 31, y = (i >> 4) & 15, x = i & 15;
    const float* plane = g_SW + ((size_t)b*128 + 64 + c)*HWN;
    out[idx] = x3[i]*(1.f + sample_sw(plane, y, x, 16));
  } else if (idx < N1+N2+N3+N4) {
    int i = idx - N1 - N2 - N3;
    int b = i >> 11, c = (i >> 6) & 31, y = (i >> 3) & 7, x = i & 7;
    const float* plane = g_SW + ((size_t)b*128 + 96 + c)*HWN;
    out[idx] = x4[i]*(1.f + sample_sw(plane, y, x, 8));
  }
}

// ===================================================================
extern "C" void kernel_launch(void* const* d_in, const int* in_sizes, int n_in,
                              void* d_out, int out_size) {
  const float* x1  = (const float*)d_in[0];
  const float* x2  = (const float*)d_in[1];
  const float* x3  = (const float*)d_in[2];
  const float* x4  = (const float*)d_in[3];
  const float* qw  = (const float*)d_in[4];
  const float* qb  = (const float*)d_in[5];
  const float* kw  = (const float*)d_in[6];
  const float* kb  = (const float*)d_in[7];
  const float* vw  = (const float*)d_in[8];
  const float* vb  = (const float*)d_in[9];
  const float* ow_ = (const float*)d_in[10];
  const float* ob  = (const float*)d_in[11];
  const float* g1w = (const float*)d_in[12];
  const float* g1b = (const float*)d_in[13];
  const float* g2w = (const float*)d_in[14];
  const float* g2b = (const float*)d_in[15];
  float* out = (float*)d_out;

  const int QKV_SMEM  = QKV_FLOATS * 4;                         // 155904 B
  const int ATTN_SMEM = STAGE_BYTES*2;                          // 36864 B
  const int PROJ_SMEM = (8192+4096+4096+128+32+128+2048+4096+1024+4096) * 4; // 111360 B

  cudaFuncSetAttribute(qkv_kernel,  cudaFuncAttributeMaxDynamicSharedMemorySize, QKV_SMEM);
  cudaFuncSetAttribute(attn_kernel, cudaFuncAttributeMaxDynamicSharedMemorySize, ATTN_SMEM);
  cudaFuncSetAttribute(proj_kernel, cudaFuncAttributeMaxDynamicSharedMemorySize, PROJ_SMEM);

  qkv_kernel <<<dim3(64, BB),  384, QKV_SMEM >>>(x1, x2, x3, x4, qw, qb, kw, kb, vw, vb);
  attn_kernel<<<dim3(32, BB),  256, ATTN_SMEM>>>();
  proj_kernel<<<dim3(128, BB), 256, PROJ_SMEM>>>(ow_, ob, g1w, g1b, g2w, g2b);

  const int TOTAL = BB*32*(4096 + 1024 + 256 + 64);  // 1392640
  gate_kernel<<<(TOTAL + 255)/256, 256>>>(x1, x2, x3, x4, out);
}

// round 8
// speedup vs baseline: 2.1692x; 1.6752x over previous
#include <cuda_runtime.h>
#include <cuda_fp16.h>
#include <math.h>
#include <stdint.h>

#define BB 8
#define HWN 4096

// -------- scratch (allocation-free rule: __device__ globals) --------
__device__ __half g_Qh[BB*HWN*64];   // [b][p][ci]
__device__ __half g_Kh[BB*HWN*64];   // [b][p][ci]
__device__ __half g_Vh[BB*64*HWN];   // [b][ci][p]  (transposed)
__device__ __half g_AOh[BB*HWN*64];  // attention output [b][p][d] (f16)
__device__ float g_SW[BB*128*HWN];   // sigmoid gates [b][ci][p]

__device__ __forceinline__ uint32_t pack_f16x2(float lo, float hi) {
  uint32_t r;
  asm("cvt.rn.f16x2.f32 %0, %1, %2;" : "=r"(r) : "f"(hi), "f"(lo));
  return r;
}

// f16 inputs, f32 accumulate
__device__ __forceinline__ void mma_f32acc(float d[4], const uint32_t a[4],
                                           uint32_t b0, uint32_t b1) {
  asm volatile("mma.sync.aligned.m16n8k16.row.col.f32.f16.f16.f32 "
               "{%0,%1,%2,%3}, {%4,%5,%6,%7}, {%8,%9}, {%0,%1,%2,%3};"
               : "+f"(d[0]), "+f"(d[1]), "+f"(d[2]), "+f"(d[3])
               : "r"(a[0]), "r"(a[1]), "r"(a[2]), "r"(a[3]), "r"(b0), "r"(b1));
}
// f16 inputs, f16 accumulate (D/C packed f16x2 -> 2 regs)
__device__ __forceinline__ void mma_f16acc(uint32_t d[2], const uint32_t a[4],
                                           uint32_t b0, uint32_t b1) {
  asm volatile("mma.sync.aligned.m16n8k16.row.col.f16.f16.f16.f16 "
               "{%0,%1}, {%2,%3,%4,%5}, {%6,%7}, {%0,%1};"
               : "+r"(d[0]), "+r"(d[1])
               : "r"(a[0]), "r"(a[1]), "r"(a[2]), "r"(a[3]), "r"(b0), "r"(b1));
}

// ===================================================================
// Kernel 1: fused gf-build (upsample+concat) + QKV 1x1 convs (tensor)
// grid (64 rows, B), 384 threads (12 warps; warp w owns out-rows 16w..16w+15)
// ===================================================================
#define QO_GFS   0
#define QO_GF16  (QO_GFS + 128*68)
#define QO_W16   (QO_GF16 + 64*68)
#define QO_BIAS  (QO_W16 + 192*68)
#define QO_OUTS  (QO_BIAS + 192)
#define QKV_FLOATS (QO_OUTS + 192*66)

__global__ void __launch_bounds__(384) qkv_kernel(
    const float* __restrict__ x1, const float* __restrict__ x2,
    const float* __restrict__ x3, const float* __restrict__ x4,
    const float* __restrict__ qw, const float* __restrict__ qb,
    const float* __restrict__ kw, const float* __restrict__ kb,
    const float* __restrict__ vw, const float* __restrict__ vb) {
  extern __shared__ float sh[];
  float*    gfs  = sh + QO_GFS;
  uint32_t* gf16 = (uint32_t*)(sh + QO_GF16);
  uint32_t* W16  = (uint32_t*)(sh + QO_W16);
  float*    bias = sh + QO_BIAS;
  float*    outs = sh + QO_OUTS;
  const int b = blockIdx.y, y = blockIdx.x, tid = threadIdx.x;

  for (int i = tid; i < 192*64; i += 384) {
    int r = i >> 6, wd = i & 63;
    const float* src = (r < 64) ? (qw + r*128) : (r < 128 ? kw + (r-64)*128 : vw + (r-128)*128);
    W16[r*68 + wd] = pack_f16x2(src[2*wd], src[2*wd+1]);
  }
  for (int i = tid; i < 192; i += 384)
    bias[i] = (i < 64) ? qb[i] : (i < 128 ? kb[i-64] : vb[i-128]);

  for (int i = tid; i < 32*64; i += 384) {
    int c = i >> 6, x = i & 63;
    gfs[c*68 + x] = x1[((b*32 + c)*64 + y)*64 + x];
  }
  const float* srcs[3] = {x2, x3, x4};
  const int    Hs[3]   = {32, 16, 8};
  #pragma unroll
  for (int lvl = 0; lvl < 3; lvl++) {
    const int H = Hs[lvl];
    const float* src = srcs[lvl];
    float fy = (float)y * (float)(H-1) / 63.0f;
    int y0 = (int)fy; if (y0 > H-1) y0 = H-1;
    int y1i = min(y0+1, H-1);
    float wy = fy - (float)y0;
    for (int i = tid; i < 32*64; i += 384) {
      int c = i >> 6, x = i & 63;
      float fx = (float)x * (float)(H-1) / 63.0f;
      int x0 = (int)fx; if (x0 > H-1) x0 = H-1;
      int x1i = min(x0+1, H-1);
      float wx = fx - (float)x0;
      const float* r0 = src + ((b*32 + c)*H + y0)*H;
      const float* r1 = src + ((b*32 + c)*H + y1i)*H;
      float top = r0[x0]*(1.f-wx) + r0[x1i]*wx;
      float bot = r1[x0]*(1.f-wx) + r1[x1i]*wx;
      gfs[(32*(lvl+1) + c)*68 + x] = top*(1.f-wy) + bot*wy;
    }
  }
  __syncthreads();

  for (int i = tid; i < 64*64; i += 384) {
    int x = i >> 6, cw = i & 63;
    gf16[x*68 + cw] = pack_f16x2(gfs[(2*cw)*68 + x], gfs[(2*cw+1)*68 + x]);
  }
  __syncthreads();

  {
    const int w = tid >> 5, lane = tid & 31;
    const int g = lane >> 2, t = lane & 3;
    uint32_t qa[8][4];
    #pragma unroll
    for (int kt = 0; kt < 8; kt++) {
      qa[kt][0] = W16[(16*w + g    )*68 + kt*8 + t];
      qa[kt][1] = W16[(16*w + g + 8)*68 + kt*8 + t];
      qa[kt][2] = W16[(16*w + g    )*68 + kt*8 + t + 4];
      qa[kt][3] = W16[(16*w + g + 8)*68 + kt*8 + t + 4];
    }
    float acc[8][4];
    #pragma unroll
    for (int nt = 0; nt < 8; nt++) { acc[nt][0]=acc[nt][1]=acc[nt][2]=acc[nt][3]=0.f; }
    #pragma unroll
    for (int kt = 0; kt < 8; kt++) {
      #pragma unroll
      for (int nt = 0; nt < 8; nt++) {
        uint32_t b0 = gf16[(8*nt + g)*68 + kt*8 + t];
        uint32_t b1 = gf16[(8*nt + g)*68 + kt*8 + t + 4];
        mma_f32acc(acc[nt], qa[kt], b0, b1);
      }
    }
    float bv0 = bias[16*w + g], bv1 = bias[16*w + g + 8];
    #pragma unroll
    for (int nt = 0; nt < 8; nt++) {
      *(float2*)&outs[(16*w + g    )*66 + 8*nt + 2*t] = make_float2(acc[nt][0]+bv0, acc[nt][1]+bv0);
      *(float2*)&outs[(16*w + g + 8)*66 + 8*nt + 2*t] = make_float2(acc[nt][2]+bv1, acc[nt][3]+bv1);
    }
  }
  __syncthreads();

  const int pbase = b*HWN + y*64;
  uint32_t* Qu = (uint32_t*)g_Qh + (size_t)pbase*32;
  uint32_t* Ku = (uint32_t*)g_Kh + (size_t)pbase*32;
  for (int i = tid; i < 2048; i += 384) {
    int p = i >> 5, c2 = i & 31;
    Qu[p*32 + c2] = pack_f16x2(outs[(2*c2)*66 + p],     outs[(2*c2+1)*66 + p]);
    Ku[p*32 + c2] = pack_f16x2(outs[(64+2*c2)*66 + p],  outs[(65+2*c2)*66 + p]);
  }
  uint32_t* Vu = (uint32_t*)g_Vh;
  for (int i = tid; i < 2048; i += 384) {
    int d = i >> 5, px = i & 31;
    const float* vr = &outs[(128+d)*66];
    Vu[((size_t)(b*64+d)*HWN + y*64)/2 + px] = pack_f16x2(vr[2*px], vr[2*px+1]);
  }
}

// ===================================================================
// Kernel 2: f16 tensor-core flash attention, half2 softmax
// grid (32 q-tiles of 128, B), 256 threads, 2 CTA/SM
// ===================================================================
#define KVW 36
#define KBYTES (64*KVW*4)
#define STAGE_BYTES (2*KBYTES)

__device__ __forceinline__ void cp_async16(uint32_t smem_dst, const void* gsrc) {
  asm volatile("cp.async.ca.shared.global [%0], [%1], 16;\n"
               :: "r"(smem_dst), "l"(gsrc));
}

__device__ __forceinline__ void prefetch_kv(uint32_t sbase, int b, int jt, int stage, int tid) {
  uint32_t st = sbase + (uint32_t)stage * STAGE_BYTES;
  const __half* Ksrc = g_Kh + ((size_t)b*HWN + jt*64)*64;
  const __half* Vsrc = g_Vh + (size_t)b*64*HWN + jt*64;
  #pragma unroll
  for (int k = 0; k < 4; k++) {
    int i = tid + k*256;
    if (i < 512) {
      int r = i >> 3, c = i & 7;
      cp_async16(st + (uint32_t)(r*KVW*4 + c*16), Ksrc + r*64 + c*8);
    } else {
      int j = i - 512, r = j >> 3, c = j & 7;
      cp_async16(st + KBYTES + (uint32_t)(r*KVW*4 + c*16), Vsrc + (size_t)r*HWN + c*8);
    }
  }
}

__global__ void __launch_bounds__(256, 2) attn_kernel() {
  extern __shared__ float sh[];
  uint32_t sbase = (uint32_t)__cvta_generic_to_shared(sh);
  const int b = blockIdx.y, m0 = blockIdx.x*128;
  const int tid = threadIdx.x, w = tid >> 5, lane = tid & 31;
  const int g = lane >> 2, t = lane & 3;

  const uint32_t* Qu = (const uint32_t*)g_Qh + ((size_t)b*HWN + m0 + w*16)*32;
  uint32_t qa[4][4];
  #pragma unroll
  for (int kt = 0; kt < 4; kt++) {
    qa[kt][0] = Qu[ g   *32 + kt*8 + t    ];
    qa[kt][1] = Qu[(g+8)*32 + kt*8 + t    ];
    qa[kt][2] = Qu[ g   *32 + kt*8 + t + 4];
    qa[kt][3] = Qu[(g+8)*32 + kt*8 + t + 4];
  }

  float m0r = -1e30f, m1r = -1e30f, l0 = 0.f, l1 = 0.f;
  float o[8][4] = {};
  const __half2 l2e2 = __float2half2_rn(1.44269504f);

  prefetch_kv(sbase, b, 0, 0, tid);
  asm volatile("cp.async.commit_group;\n" ::: "memory");

  for (int jt = 0; jt < 64; jt++) {
    if (jt + 1 < 64) {
      prefetch_kv(sbase, b, jt+1, (jt+1)&1, tid);
      asm volatile("cp.async.commit_group;\n" ::: "memory");
      asm volatile("cp.async.wait_group 1;\n" ::: "memory");
    } else {
      asm volatile("cp.async.wait_group 0;\n" ::: "memory");
    }
    __syncthreads();

    const uint32_t* Ku32 = (const uint32_t*)sh + (jt&1)*(STAGE_BYTES/4);
    const uint32_t* Vu32 = Ku32 + KBYTES/4;

    uint32_t sd[8][2];
    #pragma unroll
    for (int nt = 0; nt < 8; nt++) { sd[nt][0] = 0u; sd[nt][1] = 0u; }
    #pragma unroll
    for (int kt = 0; kt < 4; kt++) {
      #pragma unroll
      for (int nt = 0; nt < 8; nt++) {
        uint32_t b0 = Ku32[(nt*8 + g)*KVW + kt*8 + t];
        uint32_t b1 = Ku32[(nt*8 + g)*KVW + kt*8 + t + 4];
        mma_f16acc(sd[nt], qa[kt], b0, b1);
      }
    }

    __half2 hm0 = *(__half2*)&sd[0][0];
    __half2 hm1 = *(__half2*)&sd[0][1];
    #pragma unroll
    for (int nt = 1; nt < 8; nt++) {
      hm0 = __hmax2(hm0, *(__half2*)&sd[nt][0]);
      hm1 = __hmax2(hm1, *(__half2*)&sd[nt][1]);
    }
    float rmax0 = fmaxf(__low2float(hm0), __high2float(hm0));
    float rmax1 = fmaxf(__low2float(hm1), __high2float(hm1));
    rmax0 = fmaxf(rmax0, __shfl_xor_sync(0xffffffffu, rmax0, 1));
    rmax0 = fmaxf(rmax0, __shfl_xor_sync(0xffffffffu, rmax0, 2));
    rmax1 = fmaxf(rmax1, __shfl_xor_sync(0xffffffffu, rmax1, 1));
    rmax1 = fmaxf(rmax1, __shfl_xor_sync(0xffffffffu, rmax1, 2));
    float mn0 = fmaxf(m0r, rmax0), mn1 = fmaxf(m1r, rmax1);
    float c0 = __expf(m0r - mn0), c1 = __expf(m1r - mn1);
    m0r = mn0; m1r = mn1;

    __half2 off0 = __float2half2_rn(-mn0 * 1.44269504f);
    __half2 off1 = __float2half2_rn(-mn1 * 1.44269504f);
    uint32_t pe[8][2];
    #pragma unroll
    for (int nt = 0; nt < 8; nt++) {
      __half2 x0 = __hfma2(*(__half2*)&sd[nt][0], l2e2, off0);
      __half2 x1 = __hfma2(*(__half2*)&sd[nt][1], l2e2, off1);
      asm("ex2.approx.f16x2 %0, %1;" : "=r"(pe[nt][0]) : "r"(*(uint32_t*)&x0));
      asm("ex2.approx.f16x2 %0, %1;" : "=r"(pe[nt][1]) : "r"(*(uint32_t*)&x1));
    }
    __half2 sum0 = *(__half2*)&pe[0][0];
    __half2 sum1 = *(__half2*)&pe[0][1];
    #pragma unroll
    for (int nt = 1; nt < 8; nt++) {
      sum0 = __hadd2(sum0, *(__half2*)&pe[nt][0]);
      sum1 = __hadd2(sum1, *(__half2*)&pe[nt][1]);
    }
    float2 f0 = __half22float2(sum0), f1 = __half22float2(sum1);
    float rs0 = f0.x + f0.y, rs1 = f1.x + f1.y;
    rs0 += __shfl_xor_sync(0xffffffffu, rs0, 1);
    rs0 += __shfl_xor_sync(0xffffffffu, rs0, 2);
    rs1 += __shfl_xor_sync(0xffffffffu, rs1, 1);
    rs1 += __shfl_xor_sync(0xffffffffu, rs1, 2);
    l0 = l0*c0 + rs0;  l1 = l1*c1 + rs1;
    #pragma unroll
    for (int nt = 0; nt < 8; nt++) {
      o[nt][0] *= c0; o[nt][1] *= c0; o[nt][2] *= c1; o[nt][3] *= c1;
    }

    #pragma unroll
    for (int kt = 0; kt < 4; kt++) {
      uint32_t pa[4] = { pe[2*kt][0], pe[2*kt][1], pe[2*kt+1][0], pe[2*kt+1][1] };
      #pragma unroll
      for (int nt = 0; nt < 8; nt++) {
        uint32_t b0 = Vu32[(nt*8 + g)*KVW + kt*8 + t];
        uint32_t b1 = Vu32[(nt*8 + g)*KVW + kt*8 + t + 4];
        mma_f32acc(o[nt], pa, b0, b1);
      }
    }
    __syncthreads();
  }

  // AO writeout as f16 [p][64]
  uint32_t* AO = (uint32_t*)g_AOh + ((size_t)b*HWN + m0 + w*16)*32;
  float i0 = 1.f / l0, i1 = 1.f / l1;
  #pragma unroll
  for (int nt = 0; nt < 8; nt++) {
    AO[ g   *32 + nt*4 + t] = pack_f16x2(o[nt][0]*i0, o[nt][1]*i0);
    AO[(g+8)*32 + nt*4 + t] = pack_f16x2(o[nt][2]*i1, o[nt][3]*i1);
  }
}

// ===================================================================
// Kernel 3: tensor-core out-proj + gate MLP + sigmoid (AO -> g_SW)
// grid (32 pos-tiles of 128, B), 256 threads (8 warps x 16 pos rows)
// All GEMMs computed transposed (C rows = positions) so each C-frag,
// bias-added in f16x2, is stored directly as the next GEMM's fragments.
// ===================================================================
// smem float offsets; sw (f32 [128][132]) overlays dead regions
#define PJ_AO    0                      // u32 [128][36]
#define PJ_OW    (PJ_AO   + 4608)       // u32 [128][36]
#define PJ_G1W   (PJ_OW   + 4608)       // u32 [32][68]
#define PJ_GF2T  (PJ_G1W  + 2176)       // u32 [128][36]  (ends 16000)
#define PJ_SW    0                      // f32 [128][132] = 16896 (overlay)
#define PJ_G2W   16896                  // u32 [128][20]
#define PJ_HT    (PJ_G2W  + 2560)       // u32 [128][20]
#define PJ_OB16  (PJ_HT   + 2560)       // u32 [64]
#define PJ_G1B16 (PJ_OB16 + 64)         // u32 [16]
#define PJ_G2BS  (PJ_G1B16+ 16)         // f32 [128]
#define PROJ_FLOATS (PJ_G2BS + 128)     // 22224 floats = 88896 B

__global__ void __launch_bounds__(256, 2) proj_kernel(
    const float* __restrict__ ow_, const float* __restrict__ ob,
    const float* __restrict__ g1w, const float* __restrict__ g1b,
    const float* __restrict__ g2w, const float* __restrict__ g2b) {
  extern __shared__ float sh[];
  uint32_t* ao    = (uint32_t*)(sh + PJ_AO);
  uint32_t* ow36  = (uint32_t*)(sh + PJ_OW);
  uint32_t* g1w68 = (uint32_t*)(sh + PJ_G1W);
  uint32_t* gf2T  = (uint32_t*)(sh + PJ_GF2T);
  float*    sw    = sh + PJ_SW;
  uint32_t* g2w20 = (uint32_t*)(sh + PJ_G2W);
  uint32_t* hT    = (uint32_t*)(sh + PJ_HT);
  uint32_t* ob16  = (uint32_t*)(sh + PJ_OB16);
  uint32_t* g1b16 = (uint32_t*)(sh + PJ_G1B16);
  float*    g2bs  = sh + PJ_G2BS;

  const int b = blockIdx.y, p0 = blockIdx.x*128, tid = threadIdx.x;
  const int w = tid >> 5, lane = tid & 31;
  const int g = lane >> 2, t = lane & 3;

  // ---- stage inputs ----
  const uint32_t* AOg = (const uint32_t*)g_AOh + ((size_t)b*HWN + p0)*32;
  for (int i = tid; i < 4096; i += 256) {           // AO f16 [128][32w]
    int r = i >> 5, wd = i & 31;
    ao[r*36 + wd] = AOg[r*32 + wd];
  }
  for (int i = tid; i < 4096; i += 256) {           // ow_ [128][64] -> f16
    int r = i >> 5, wd = i & 31;
    ow36[r*36 + wd] = pack_f16x2(ow_[r*64 + 2*wd], ow_[r*64 + 2*wd + 1]);
  }
  for (int i = tid; i < 2048; i += 256) {           // g1w [32][128] -> f16
    int r = i >> 6, wd = i & 63;
    g1w68[r*68 + wd] = pack_f16x2(g1w[r*128 + 2*wd], g1w[r*128 + 2*wd + 1]);
  }
  for (int i = tid; i < 2048; i += 256) {           // g2w [128][32] -> f16
    int r = i >> 4, wd = i & 15;
    g2w20[r*20 + wd] = pack_f16x2(g2w[r*32 + 2*wd], g2w[r*32 + 2*wd + 1]);
  }
  for (int i = tid; i < 64;  i += 256) ob16[i]  = pack_f16x2(ob[2*i],  ob[2*i+1]);
  for (int i = tid; i < 16;  i += 256) g1b16[i] = pack_f16x2(g1b[2*i], g1b[2*i+1]);
  for (int i = tid; i < 128; i += 256) g2bs[i]  = g2b[i];
  __syncthreads();

  // ---- GEMM1: gf2T[pos][o] = AO[pos][d] * ow[o][d]^T + ob ----
  {
    uint32_t qa[4][4];
    #pragma unroll
    for (int kt = 0; kt < 4; kt++) {
      qa[kt][0] = ao[(16*w + g    )*36 + kt*8 + t];
      qa[kt][1] = ao[(16*w + g + 8)*36 + kt*8 + t];
      qa[kt][2] = ao[(16*w + g    )*36 + kt*8 + t + 4];
      qa[kt][3] = ao[(16*w + g + 8)*36 + kt*8 + t + 4];
    }
    uint32_t sd[16][2];
    #pragma unroll
    for (int nt = 0; nt < 16; nt++) { sd[nt][0] = 0u; sd[nt][1] = 0u; }
    #pragma unroll
    for (int kt = 0; kt < 4; kt++) {
      #pragma unroll
      for (int nt = 0; nt < 16; nt++) {
        uint32_t b0 = ow36[(nt*8 + g)*36 + kt*8 + t];
        uint32_t b1 = ow36[(nt*8 + g)*36 + kt*8 + t + 4];
        mma_f16acc(sd[nt], qa[kt], b0, b1);
      }
    }
    #pragma unroll
    for (int nt = 0; nt < 16; nt++) {
      __half2 bb = *(__half2*)&ob16[nt*4 + t];
      __half2 v0 = __hadd2(*(__half2*)&sd[nt][0], bb);
      __half2 v1 = __hadd2(*(__half2*)&sd[nt][1], bb);
      gf2T[(16*w + g    )*36 + nt*4 + t] = *(uint32_t*)&v0;
      gf2T[(16*w + g + 8)*36 + nt*4 + t] = *(uint32_t*)&v1;
    }
  }
  __syncwarp();

  // ---- GEMM2: hT[pos][co] = relu(gf2T[pos][c] * g1w[co][c]^T + g1b) ----
  uint32_t qa3[2][4];
  {
    uint32_t qa2[8][4];
    #pragma unroll
    for (int kt = 0; kt < 8; kt++) {
      qa2[kt][0] = gf2T[(16*w + g    )*36 + kt*8 + t];
      qa2[kt][1] = gf2T[(16*w + g + 8)*36 + kt*8 + t];
      qa2[kt][2] = gf2T[(16*w + g    )*36 + kt*8 + t + 4];
      qa2[kt][3] = gf2T[(16*w + g + 8)*36 + kt*8 + t + 4];
    }
    uint32_t sd2[4][2];
    #pragma unroll
    for (int nt = 0; nt < 4; nt++) { sd2[nt][0] = 0u; sd2[nt][1] = 0u; }
    #pragma unroll
    for (int kt = 0; kt < 8; kt++) {
      #pragma unroll
      for (int nt = 0; nt < 4; nt++) {
        uint32_t b0 = g1w68[(nt*8 + g)*68 + kt*8 + t];
        uint32_t b1 = g1w68[(nt*8 + g)*68 + kt*8 + t + 4];
        mma_f16acc(sd2[nt], qa2[kt], b0, b1);
      }
    }
    const __half2 z2 = __float2half2_rn(0.f);
    #pragma unroll
    for (int nt = 0; nt < 4; nt++) {
      __half2 bb = *(__half2*)&g1b16[nt*4 + t];
      __half2 v0 = __hmax2(__hadd2(*(__half2*)&sd2[nt][0], bb), z2);
      __half2 v1 = __hmax2(__hadd2(*(__half2*)&sd2[nt][1], bb), z2);
      hT[(16*w + g    )*20 + nt*4 + t] = *(uint32_t*)&v0;
      hT[(16*w + g + 8)*20 + nt*4 + t] = *(uint32_t*)&v1;
    }
    __syncwarp();
    #pragma unroll
    for (int kt = 0; kt < 2; kt++) {
      qa3[kt][0] = hT[(16*w + g    )*20 + kt*8 + t];
      qa3[kt][1] = hT[(16*w + g + 8)*20 + kt*8 + t];
      qa3[kt][2] = hT[(16*w + g    )*20 + kt*8 + t + 4];
      qa3[kt][3] = hT[(16*w + g + 8)*20 + kt*8 + t + 4];
    }
  }
  __syncthreads();   // everyone done with ao/ow/g1w/gf2T before sw overlay

  // ---- GEMM3: sw[ci][pos] = sigmoid(hT[pos][co] * g2w[ci][co]^T + g2b) ----
  #pragma unroll
  for (int half = 0; half < 2; half++) {
    float acc[8][4];
    #pragma unroll
    for (int nt = 0; nt < 8; nt++) { acc[nt][0]=acc[nt][1]=acc[nt][2]=acc[nt][3]=0.f; }
    #pragma unroll
    for (int kt = 0; kt < 2; kt++) {
      #pragma unroll
      for (int nt = 0; nt < 8; nt++) {
        int ntg = half*8 + nt;
        uint32_t b0 = g2w20[(ntg*8 + g)*20 + kt*8 + t];
        uint32_t b1 = g2w20[(ntg*8 + g)*20 + kt*8 + t + 4];
        mma_f32acc(acc[nt], qa3[kt], b0, b1);
      }
    }
    #pragma unroll
    for (int nt = 0; nt < 8; nt++) {
      int ci0 = (half*8 + nt)*8 + 2*t, ci1 = ci0 + 1;
      sw[ci0*132 + 16*w + g    ] = 1.f/(1.f + __expf(-(acc[nt][0] + g2bs[ci0])));
      sw[ci1*132 + 16*w + g    ] = 1.f/(1.f + __expf(-(acc[nt][1] + g2bs[ci1])));
      sw[ci0*132 + 16*w + g + 8] = 1.f/(1.f + __expf(-(acc[nt][2] + g2bs[ci0])));
      sw[ci1*132 + 16*w + g + 8] = 1.f/(1.f + __expf(-(acc[nt][3] + g2bs[ci1])));
    }
  }
  __syncthreads();

  // ---- coalesced copy-out: sw [128ci][128pos] -> g_SW [b][ci][p] ----
  for (int i = tid; i < 4096; i += 256) {
    int ci = i >> 5, pq = i & 31;
    float4 v = *(float4*)&sw[ci*132 + 4*pq];
    *(float4*)&g_SW[((size_t)b*128 + ci)*HWN + p0 + 4*pq] = v;
  }
}

// ===================================================================
// Kernel 4: final gating (with bilinear resample of gates for x2..x4)
// ===================================================================
__device__ __forceinline__ float sample_sw(const float* __restrict__ plane, int y, int x, int OH) {
  float fy = (float)y * 63.0f / (float)(OH-1);
  float fx = (float)x * 63.0f / (float)(OH-1);
  int y0 = (int)fy; if (y0 > 63) y0 = 63;
  int x0 = (int)fx; if (x0 > 63) x0 = 63;
  int y1 = min(y0+1, 63), x1 = min(x0+1, 63);
  float wy = fy - (float)y0, wx = fx - (float)x0;
  float a = plane[y0*64+x0], bv = plane[y0*64+x1];
  float c = plane[y1*64+x0], d = plane[y1*64+x1];
  return (a*(1.f-wx)+bv*wx)*(1.f-wy) + (c*(1.f-wx)+d*wx)*wy;
}

__global__ void gate_kernel(const float* __restrict__ x1, const float* __restrict__ x2,
                            const float* __restrict__ x3, const float* __restrict__ x4,
                            float* __restrict__ out) {
  int idx = blockIdx.x*256 + threadIdx.x;
  const int N1 = BB*32*4096, N2 = BB*32*1024, N3 = BB*32*256, N4 = BB*32*64;
  if (idx < N1) {
    int b = idx >> 17, c = (idx >> 12) & 31, p = idx & 4095;
    out[idx] = x1[idx]*(1.f + g_SW[((size_t)b*128 + c)*HWN + p]);
  } else if (idx < N1+N2) {
    int i = idx - N1;
    int b = i >> 15, c = (i >> 10) & 31, y = (i >> 5) & 31, x = i & 31;
    const float* plane = g_SW + ((size_t)b*128 + 32 + c)*HWN;
    out[idx] = x2[i]*(1.f + sample_sw(plane, y, x, 32));
  } else if (idx < N1+N2+N3) {
    int i = idx - N1 - N2;
    int b = i >> 13, c = (i >> 8) & 31, y = (i >> 4) & 15, x = i & 15;
    const float* plane = g_SW + ((size_t)b*128 + 64 + c)*HWN;
    out[idx] = x3[i]*(1.f + sample_sw(plane, y, x, 16));
  } else if (idx < N1+N2+N3+N4) {
    int i = idx - N1 - N2 - N3;
    int b = i >> 11, c = (i >> 6) & 31, y = (i >> 3) & 7, x = i & 7;
    const float* plane = g_SW + ((size_t)b*128 + 96 + c)*HWN;
    out[idx] = x4[i]*(1.f + sample_sw(plane, y, x, 8));
  }
}

// ===================================================================
extern "C" void kernel_launch(void* const* d_in, const int* in_sizes, int n_in,
                              void* d_out, int out_size) {
  const float* x1  = (const float*)d_in[0];
  const float* x2  = (const float*)d_in[1];
  const float* x3  = (const float*)d_in[2];
  const float* x4  = (const float*)d_in[3];
  const float* qw  = (const float*)d_in[4];
  const float* qb  = (const float*)d_in[5];
  const float* kw  = (const float*)d_in[6];
  const float* kb  = (const float*)d_in[7];
  const float* vw  = (const float*)d_in[8];
  const float* vb  = (const float*)d_in[9];
  const float* ow_ = (const float*)d_in[10];
  const float* ob  = (const float*)d_in[11];
  const float* g1w = (const float*)d_in[12];
  const float* g1b = (const float*)d_in[13];
  const float* g2w = (const float*)d_in[14];
  const float* g2b = (const float*)d_in[15];
  float* out = (float*)d_out;

  const int QKV_SMEM  = QKV_FLOATS * 4;   // 155904 B
  const int ATTN_SMEM = STAGE_BYTES*2;    // 36864 B
  const int PROJ_SMEM = PROJ_FLOATS * 4;  // 88896 B

  cudaFuncSetAttribute(qkv_kernel,  cudaFuncAttributeMaxDynamicSharedMemorySize, QKV_SMEM);
  cudaFuncSetAttribute(attn_kernel, cudaFuncAttributeMaxDynamicSharedMemorySize, ATTN_SMEM);
  cudaFuncSetAttribute(proj_kernel, cudaFuncAttributeMaxDynamicSharedMemorySize, PROJ_SMEM);

  qkv_kernel <<<dim3(64, BB), 384, QKV_SMEM >>>(x1, x2, x3, x4, qw, qb, kw, kb, vw, vb);
  attn_kernel<<<dim3(32, BB), 256, ATTN_SMEM>>>();
  proj_kernel<<<dim3(32, BB), 256, PROJ_SMEM>>>(ow_, ob, g1w, g1b, g2w, g2b);

  const int TOTAL = BB*32*(4096 + 1024 + 256 + 64);  // 1392640
  gate_kernel<<<(TOTAL + 255)/256, 256>>>(x1, x2, x3, x4, out);
}